// round 1
// baseline (speedup 1.0000x reference)
#include <cuda_runtime.h>
#include <math.h>

#define BS_    2
#define NQ_    4096
#define DIM_   768
#define HEADS_ 6
#define POINTS_ 4
#define HD_    128
#define HW_    64
#define NROWS_ (BS_*NQ_)   // 8192

// ---------------- scratch (no allocations allowed) ----------------
__device__ float g_qn   [NROWS_*DIM_];   // layernormed query
__device__ float g_value[NROWS_*DIM_];   // feat @ vp_w + vp_b
__device__ float g_attn [NROWS_*DIM_];   // sampled attention output
__device__ float g_loc  [NROWS_*HEADS_*POINTS_*2];
__device__ float g_aw   [NROWS_*HEADS_*POINTS_];

// ---------------- 1) LayerNorm ----------------
__global__ __launch_bounds__(256) void ln_kernel(
    const float* __restrict__ query,
    const float* __restrict__ w, const float* __restrict__ b)
{
    int row = blockIdx.x;
    int tid = threadIdx.x;
    const float* x = query + (size_t)row * DIM_;
    float v0 = x[tid], v1 = x[tid + 256], v2 = x[tid + 512];
    float s = v0 + v1 + v2;
    __shared__ float red[8];
    __shared__ float red2[8];
    #pragma unroll
    for (int o = 16; o; o >>= 1) s += __shfl_xor_sync(0xffffffffu, s, o);
    if ((tid & 31) == 0) red[tid >> 5] = s;
    __syncthreads();
    if (tid < 32) {
        float t = (tid < 8) ? red[tid] : 0.f;
        #pragma unroll
        for (int o = 4; o; o >>= 1) t += __shfl_xor_sync(0xffffffffu, t, o);
        if (tid == 0) red[0] = t;
    }
    __syncthreads();
    float mean = red[0] * (1.f / DIM_);
    float d0 = v0 - mean, d1 = v1 - mean, d2 = v2 - mean;
    s = d0 * d0 + d1 * d1 + d2 * d2;
    #pragma unroll
    for (int o = 16; o; o >>= 1) s += __shfl_xor_sync(0xffffffffu, s, o);
    if ((tid & 31) == 0) red2[tid >> 5] = s;
    __syncthreads();
    if (tid < 32) {
        float t = (tid < 8) ? red2[tid] : 0.f;
        #pragma unroll
        for (int o = 4; o; o >>= 1) t += __shfl_xor_sync(0xffffffffu, t, o);
        if (tid == 0) red2[0] = t;
    }
    __syncthreads();
    float rstd = rsqrtf(red2[0] * (1.f / DIM_) + 1e-6f);
    float* o = g_qn + (size_t)row * DIM_;
    o[tid]       = d0 * rstd * w[tid]       + b[tid];
    o[tid + 256] = d1 * rstd * w[tid + 256] + b[tid + 256];
    o[tid + 512] = d2 * rstd * w[tid + 512] + b[tid + 512];
}

// ---------------- 2 & 5) SGEMM  C[8192x768] = A[8192x768] @ B[768x768] ----------------
// MODE 0: C = acc + bias
// MODE 1: C = resid + gamma * (acc + bias)
template <int MODE>
__global__ __launch_bounds__(256) void sgemm_kernel(
    const float* __restrict__ A, const float* __restrict__ B,
    const float* __restrict__ bias, float* __restrict__ C,
    const float* __restrict__ resid, const float* __restrict__ gamma)
{
    const int K = DIM_, N = DIM_;
    __shared__ float As[8][128];
    __shared__ float Bs[8][128];
    int tid = threadIdx.x;
    int tx = tid & 15, ty = tid >> 4;
    int bx = blockIdx.x, by = blockIdx.y;
    const float* Ab = A + (size_t)(by * 128) * K;
    const float* Bb = B + bx * 128;
    float acc[8][8] = {};
    int arow = tid >> 1, ac4 = (tid & 1) * 4;
    int brow = tid >> 5, bc4 = (tid & 31) * 4;
    for (int k0 = 0; k0 < K; k0 += 8) {
        float4 av = *(const float4*)(Ab + (size_t)arow * K + k0 + ac4);
        As[ac4 + 0][arow] = av.x; As[ac4 + 1][arow] = av.y;
        As[ac4 + 2][arow] = av.z; As[ac4 + 3][arow] = av.w;
        float4 bv = *(const float4*)(Bb + (size_t)(k0 + brow) * N + bc4);
        *(float4*)&Bs[brow][bc4] = bv;
        __syncthreads();
        #pragma unroll
        for (int k = 0; k < 8; k++) {
            float a[8], bb[8];
            *(float4*)(a)     = *(const float4*)&As[k][ty * 8];
            *(float4*)(a + 4) = *(const float4*)&As[k][ty * 8 + 4];
            *(float4*)(bb)     = *(const float4*)&Bs[k][tx * 8];
            *(float4*)(bb + 4) = *(const float4*)&Bs[k][tx * 8 + 4];
            #pragma unroll
            for (int i = 0; i < 8; i++)
                #pragma unroll
                for (int j = 0; j < 8; j++)
                    acc[i][j] = fmaf(a[i], bb[j], acc[i][j]);
        }
        __syncthreads();
    }
    int row0 = by * 128 + ty * 8;
    int col0 = bx * 128 + tx * 8;
    #pragma unroll
    for (int i = 0; i < 8; i++) {
        int row = row0 + i;
        float out[8];
        #pragma unroll
        for (int j = 0; j < 8; j++) {
            float v = acc[i][j] + bias[col0 + j];
            if (MODE == 1)
                v = resid[(size_t)row * N + col0 + j] + gamma[col0 + j] * v;
            out[j] = v;
        }
        *(float4*)(C + (size_t)row * N + col0)     = *(float4*)(out);
        *(float4*)(C + (size_t)row * N + col0 + 4) = *(float4*)(out + 4);
    }
}

// ---------------- 3) offset/attention-weight projection + softmax + locations ----------
// Tiled GEMM: 128 queries per block x 72 outputs, K=768. Then per-row softmax(24) + loc.
__global__ __launch_bounds__(256) void offaw_kernel(
    const float* __restrict__ refp,
    const float* __restrict__ offw, const float* __restrict__ offb,
    const float* __restrict__ aww,  const float* __restrict__ awb)
{
    __shared__ __align__(16) char sbuf[37376];
    float (*As)[128] = (float(*)[128])sbuf;            // 16x128 = 8192 B
    float (*Bs)[72]  = (float(*)[72])(sbuf + 8192);    // 16x72  = 4608 B
    float (*Ls)[73]  = (float(*)[73])sbuf;             // 128x73 = 37376 B (reused after loop)

    int tid = threadIdx.x;
    int by = blockIdx.x;
    int tx = tid & 7;    // 8 col groups x 9
    int ty = tid >> 3;   // 32 row groups x 4
    float acc[4][9] = {};
    const float* Ab = g_qn + (size_t)by * 128 * DIM_;

    for (int k0 = 0; k0 < DIM_; k0 += 16) {
        #pragma unroll
        for (int u = 0; u < 2; u++) {
            int p = tid * 2 + u;
            int r = p >> 2, c4 = (p & 3) * 4;
            float4 v = *(const float4*)(Ab + (size_t)r * DIM_ + k0 + c4);
            As[c4 + 0][r] = v.x; As[c4 + 1][r] = v.y;
            As[c4 + 2][r] = v.z; As[c4 + 3][r] = v.w;
        }
        for (int idx = tid; idx < 16 * 72; idx += 256) {
            int r = idx / 72, c = idx % 72;
            Bs[r][c] = (c < 48) ? offw[(size_t)(k0 + r) * 48 + c]
                                : aww[(size_t)(k0 + r) * 24 + (c - 48)];
        }
        __syncthreads();
        #pragma unroll
        for (int k = 0; k < 16; k++) {
            float a[4], bb[9];
            #pragma unroll
            for (int i = 0; i < 4; i++) a[i] = As[k][ty * 4 + i];
            #pragma unroll
            for (int j = 0; j < 9; j++) bb[j] = Bs[k][tx * 9 + j];
            #pragma unroll
            for (int i = 0; i < 4; i++)
                #pragma unroll
                for (int j = 0; j < 9; j++)
                    acc[i][j] = fmaf(a[i], bb[j], acc[i][j]);
        }
        __syncthreads();
    }
    // write logits (+bias) into Ls (aliases As/Bs, safe after last sync)
    #pragma unroll
    for (int i = 0; i < 4; i++)
        #pragma unroll
        for (int j = 0; j < 9; j++) {
            int c = tx * 9 + j;
            float bias = (c < 48) ? offb[c] : awb[c - 48];
            Ls[ty * 4 + i][c] = acc[i][j] + bias;
        }
    __syncthreads();

    int warp = tid >> 5, lane = tid & 31;
    for (int r = warp; r < 128; r += 8) {
        int qi = by * 128 + r;
        // softmax over the 24 attention logits (cols 48..71)
        float x = (lane < 24) ? Ls[r][48 + lane] : -1e30f;
        float m = x;
        #pragma unroll
        for (int o = 16; o; o >>= 1) m = fmaxf(m, __shfl_xor_sync(0xffffffffu, m, o));
        float e = (lane < 24) ? __expf(x - m) : 0.f;
        float ssum = e;
        #pragma unroll
        for (int o = 16; o; o >>= 1) ssum += __shfl_xor_sync(0xffffffffu, ssum, o);
        if (lane < 24) g_aw[(size_t)qi * 24 + lane] = e / ssum;
        // sampling locations: loc = ref + offset / 64   (norm [W,H] = [64,64])
        float rx = refp[(size_t)qi * 2 + 0];
        float ry = refp[(size_t)qi * 2 + 1];
        for (int j = lane; j < 48; j += 32) {
            float ref = (j & 1) ? ry : rx;
            g_loc[(size_t)qi * 48 + j] = ref + Ls[r][j] * (1.f / 64.f);
        }
    }
}

// ---------------- 4) bilinear sampling: one warp per (query, head) ----------------
__global__ __launch_bounds__(256) void sample_kernel()
{
    int w = blockIdx.x * 8 + (threadIdx.x >> 5);
    int lane = threadIdx.x & 31;
    int h  = w % HEADS_;
    int qi = w / HEADS_;          // 0..8191 == b*4096 + nq
    int b  = qi >> 12;
    float a0 = 0.f, a1 = 0.f, a2 = 0.f, a3 = 0.f;
    const float* val = g_value + (size_t)b * NQ_ * DIM_ + h * HD_;
    #pragma unroll
    for (int p = 0; p < POINTS_; p++) {
        float lx = g_loc[(size_t)qi * 48 + (h * POINTS_ + p) * 2 + 0];
        float ly = g_loc[(size_t)qi * 48 + (h * POINTS_ + p) * 2 + 1];
        float aw = g_aw[(size_t)qi * 24 + h * POINTS_ + p];
        float xf = lx * HW_ - 0.5f;
        float yf = ly * HW_ - 0.5f;
        float x0f = floorf(xf), y0f = floorf(yf);
        float wx = xf - x0f, wy = yf - y0f;
        int x0 = (int)x0f, y0 = (int)y0f;
        #pragma unroll
        for (int dy = 0; dy < 2; dy++) {
            #pragma unroll
            for (int dx = 0; dx < 2; dx++) {
                int xi = x0 + dx, yi = y0 + dy;
                if (xi < 0 || xi >= HW_ || yi < 0 || yi >= HW_) continue;
                float cw = aw * (dy ? wy : 1.f - wy) * (dx ? wx : 1.f - wx);
                const float* vv = val + (size_t)(yi * HW_ + xi) * DIM_;
                a0 = fmaf(cw, vv[lane],      a0);
                a1 = fmaf(cw, vv[lane + 32], a1);
                a2 = fmaf(cw, vv[lane + 64], a2);
                a3 = fmaf(cw, vv[lane + 96], a3);
            }
        }
    }
    float* o = g_attn + (size_t)qi * DIM_ + h * HD_;
    o[lane]      = a0;
    o[lane + 32] = a1;
    o[lane + 64] = a2;
    o[lane + 96] = a3;
}

// ---------------- launch ----------------
extern "C" void kernel_launch(void* const* d_in, const int* in_sizes, int n_in,
                              void* d_out, int out_size)
{
    const float* query = (const float*)d_in[0];
    const float* refp  = (const float*)d_in[1];
    const float* feat  = (const float*)d_in[2];
    // d_in[3] spatial_shapes (int64, = [[64,64]]), d_in[4] level_start_index: compile-time known
    const float* lnw  = (const float*)d_in[5];
    const float* lnb  = (const float*)d_in[6];
    const float* vpw  = (const float*)d_in[7];
    const float* vpb  = (const float*)d_in[8];
    const float* offw = (const float*)d_in[9];
    const float* offb = (const float*)d_in[10];
    const float* aww  = (const float*)d_in[11];
    const float* awb  = (const float*)d_in[12];
    const float* outw = (const float*)d_in[13];
    const float* outb = (const float*)d_in[14];
    const float* gamma= (const float*)d_in[15];
    float* out = (float*)d_out;

    float *p_value, *p_attn;
    cudaGetSymbolAddress((void**)&p_value, g_value);
    cudaGetSymbolAddress((void**)&p_attn,  g_attn);

    dim3 gg(DIM_ / 128, NROWS_ / 128);   // (6, 64)

    ln_kernel<<<NROWS_, 256>>>(query, lnw, lnb);
    sgemm_kernel<0><<<gg, 256>>>(feat, vpw, vpb, p_value, nullptr, nullptr);
    offaw_kernel<<<NROWS_ / 128, 256>>>(refp, offw, offb, aww, awb);
    sample_kernel<<<NROWS_ * HEADS_ / 8, 256>>>();
    sgemm_kernel<1><<<gg, 256>>>(p_attn, outw, outb, out, query, gamma);
}

// round 3
// speedup vs baseline: 1.8708x; 1.8708x over previous
#include <cuda_runtime.h>
#include <cuda_bf16.h>
#include <math.h>
#include <cstdint>

#define BS_    2
#define NQ_    4096
#define DIM_   768
#define HEADS_ 6
#define POINTS_ 4
#define HD_    128
#define HW_    64
#define NROWS_ (BS_*NQ_)   // 8192

// ---------------- scratch (no allocations allowed) ----------------
__device__ __align__(128) float         g_qn   [NROWS_*DIM_];
__device__ __align__(128) __nv_bfloat16 g_featb[NROWS_*DIM_];
__device__ __align__(128) __nv_bfloat16 g_valb [NROWS_*DIM_];
__device__ __align__(128) __nv_bfloat16 g_attnb[NROWS_*DIM_];
__device__ __align__(128) __nv_bfloat16 g_vpwt [DIM_*DIM_];     // vp_w^T  [N,K]
__device__ __align__(128) __nv_bfloat16 g_outwt[DIM_*DIM_];     // out_w^T [N,K]
__device__ __align__(128) float g_loc [NROWS_*HEADS_*POINTS_*2];
__device__ __align__(128) float g_aw  [NROWS_*HEADS_*POINTS_];

// ================= PTX helpers =================
__device__ __forceinline__ uint32_t smem_u32(const void* p) {
    uint32_t a;
    asm("{ .reg .u64 t; cvta.to.shared.u64 t, %1; cvt.u32.u64 %0, t; }" : "=r"(a) : "l"(p));
    return a;
}
__device__ __forceinline__ void cp16(uint32_t dst, const void* src) {
    asm volatile("cp.async.cg.shared.global [%0], [%1], 16;" :: "r"(dst), "l"(src));
}
#define CP_COMMIT() asm volatile("cp.async.commit_group;" ::: "memory")

__device__ __forceinline__ void ldsm4(uint32_t& r0, uint32_t& r1, uint32_t& r2, uint32_t& r3,
                                      uint32_t addr) {
    asm volatile("ldmatrix.sync.aligned.m8n8.x4.shared.b16 {%0,%1,%2,%3}, [%4];"
                 : "=r"(r0), "=r"(r1), "=r"(r2), "=r"(r3) : "r"(addr));
}
__device__ __forceinline__ void mma_bf16(float* c, const uint32_t* a, const uint32_t* b) {
    asm volatile("mma.sync.aligned.m16n8k16.row.col.f32.bf16.bf16.f32 "
                 "{%0,%1,%2,%3}, {%4,%5,%6,%7}, {%8,%9}, {%0,%1,%2,%3};"
                 : "+f"(c[0]), "+f"(c[1]), "+f"(c[2]), "+f"(c[3])
                 : "r"(a[0]), "r"(a[1]), "r"(a[2]), "r"(a[3]), "r"(b[0]), "r"(b[1]));
}

// ---------------- 1) LayerNorm ----------------
__global__ __launch_bounds__(256) void ln_kernel(
    const float* __restrict__ query,
    const float* __restrict__ w, const float* __restrict__ b)
{
    int row = blockIdx.x;
    int tid = threadIdx.x;
    const float* x = query + (size_t)row * DIM_;
    float v0 = x[tid], v1 = x[tid + 256], v2 = x[tid + 512];
    float s = v0 + v1 + v2;
    __shared__ float red[8];
    __shared__ float red2[8];
    #pragma unroll
    for (int o = 16; o; o >>= 1) s += __shfl_xor_sync(0xffffffffu, s, o);
    if ((tid & 31) == 0) red[tid >> 5] = s;
    __syncthreads();
    if (tid < 32) {
        float t = (tid < 8) ? red[tid] : 0.f;
        #pragma unroll
        for (int o = 4; o; o >>= 1) t += __shfl_xor_sync(0xffffffffu, t, o);
        if (tid == 0) red[0] = t;
    }
    __syncthreads();
    float mean = red[0] * (1.f / DIM_);
    float d0 = v0 - mean, d1 = v1 - mean, d2 = v2 - mean;
    s = d0 * d0 + d1 * d1 + d2 * d2;
    #pragma unroll
    for (int o = 16; o; o >>= 1) s += __shfl_xor_sync(0xffffffffu, s, o);
    if ((tid & 31) == 0) red2[tid >> 5] = s;
    __syncthreads();
    if (tid < 32) {
        float t = (tid < 8) ? red2[tid] : 0.f;
        #pragma unroll
        for (int o = 4; o; o >>= 1) t += __shfl_xor_sync(0xffffffffu, t, o);
        if (tid == 0) red2[0] = t;
    }
    __syncthreads();
    float rstd = rsqrtf(red2[0] * (1.f / DIM_) + 1e-6f);
    float* o = g_qn + (size_t)row * DIM_;
    o[tid]       = d0 * rstd * w[tid]       + b[tid];
    o[tid + 256] = d1 * rstd * w[tid + 256] + b[tid + 256];
    o[tid + 512] = d2 * rstd * w[tid + 512] + b[tid + 512];
}

// ---------------- fp32 -> bf16 convert ----------------
__global__ __launch_bounds__(256) void convA_kernel(
    const float4* __restrict__ in, uint2* __restrict__ out, int n4)
{
    int i = blockIdx.x * 256 + threadIdx.x;
    if (i >= n4) return;
    float4 v = in[i];
    uint32_t lo, hi;
    asm("cvt.rn.bf16x2.f32 %0, %1, %2;" : "=r"(lo) : "f"(v.y), "f"(v.x));
    asm("cvt.rn.bf16x2.f32 %0, %1, %2;" : "=r"(hi) : "f"(v.w), "f"(v.z));
    out[i] = make_uint2(lo, hi);
}

// ---------------- transpose + convert weight: Wt[n][k] = W[k][n] ----------------
__global__ __launch_bounds__(256) void convT_kernel(
    const float* __restrict__ W, __nv_bfloat16* __restrict__ Wt)
{
    __shared__ float t[32][33];
    int bx = blockIdx.x * 32, by = blockIdx.y * 32;
    int tx = threadIdx.x, ty = threadIdx.y;
    #pragma unroll
    for (int i = 0; i < 32; i += 8)
        t[ty + i][tx] = W[(size_t)(by + ty + i) * DIM_ + bx + tx];
    __syncthreads();
    #pragma unroll
    for (int i = 0; i < 32; i += 8)
        Wt[(size_t)(bx + ty + i) * DIM_ + by + tx] = __float2bfloat16(t[tx][ty + i]);
}

// ---------------- HMMA bf16 GEMM: C[8192x768] = A @ Bt^T --------------------------
// CTA tile 128x128, warp tile 32x64, K-chunk 32, 4-stage cp.async pipeline.
// MODE 0: C = bf16(acc + bias)          (C is bf16)
// MODE 1: C = fp32(resid + gamma*(acc + bias))   (C is fp32)
#define KC       32
#define RSE      40              // row stride in elements (32 + 8 pad)
#define RSB      80              // row stride bytes
#define STAGE_B  (2 * 128 * RSB) // A tile + B tile per stage = 20480
#define NSTEP    (DIM_ / KC)     // 24

template <int MODE>
__global__ __launch_bounds__(256) void gemm_bf16(
    const __nv_bfloat16* __restrict__ A, const __nv_bfloat16* __restrict__ Bt,
    const float* __restrict__ bias, void* __restrict__ Cout,
    const float* __restrict__ resid, const float* __restrict__ gamma)
{
    extern __shared__ __align__(128) char dsm[];
    uint32_t sb = smem_u32(dsm);
    int tid = threadIdx.x, wid = tid >> 5, lane = tid & 31;
    int n0 = blockIdx.x * 128, m0 = blockIdx.y * 128;
    int wm = (wid & 3) * 32;     // warp m offset
    int wn = (wid >> 2) * 64;    // warp n offset

    // per-thread cp.async slots: 2 A chunks + 2 B chunks per stage
    int lrow[2], lc[2];
    #pragma unroll
    for (int j = 0; j < 2; j++) {
        int id = j * 256 + tid;
        lrow[j] = id >> 2;          // 0..127
        lc[j]   = (id & 3) * 8;     // k element offset 0,8,16,24
    }

    auto load_stage = [&](int s) {
        uint32_t base = sb + (s & 3) * STAGE_B;
        int k0 = s * KC;
        #pragma unroll
        for (int j = 0; j < 2; j++)
            cp16(base + lrow[j] * RSB + lc[j] * 2,
                 A + (size_t)(m0 + lrow[j]) * DIM_ + k0 + lc[j]);
        #pragma unroll
        for (int j = 0; j < 2; j++)
            cp16(base + 128 * RSB + lrow[j] * RSB + lc[j] * 2,
                 Bt + (size_t)(n0 + lrow[j]) * DIM_ + k0 + lc[j]);
        CP_COMMIT();
    };

    float acc[2][8][4] = {};

    load_stage(0); load_stage(1); load_stage(2);

    for (int s = 0; s < NSTEP; s++) {
        if (s + 3 < NSTEP) {
            load_stage(s + 3);
            asm volatile("cp.async.wait_group 3;" ::: "memory");
        } else if (s + 3 == NSTEP) {
            asm volatile("cp.async.wait_group 2;" ::: "memory");
        } else if (s + 2 == NSTEP) {
            asm volatile("cp.async.wait_group 1;" ::: "memory");
        } else {
            asm volatile("cp.async.wait_group 0;" ::: "memory");
        }
        __syncthreads();

        uint32_t abase = sb + (s & 3) * STAGE_B;
        uint32_t bbase = abase + 128 * RSB;
        #pragma unroll
        for (int kk = 0; kk < 2; kk++) {
            uint32_t af[2][4], bf[4][4];
            #pragma unroll
            for (int mt = 0; mt < 2; mt++) {
                int r  = wm + mt * 16 + (lane & 15);
                int kc = kk * 16 + (lane >> 4) * 8;
                ldsm4(af[mt][0], af[mt][1], af[mt][2], af[mt][3],
                      abase + r * RSB + kc * 2);
            }
            #pragma unroll
            for (int np = 0; np < 4; np++) {
                int n  = wn + np * 16 + (lane & 7) + ((lane >> 4) << 3);
                int kc = kk * 16 + ((lane >> 3) & 1) * 8;
                ldsm4(bf[np][0], bf[np][1], bf[np][2], bf[np][3],
                      bbase + n * RSB + kc * 2);
            }
            #pragma unroll
            for (int mt = 0; mt < 2; mt++)
                #pragma unroll
                for (int nt = 0; nt < 8; nt++)
                    mma_bf16(acc[mt][nt], af[mt], &bf[nt >> 1][(nt & 1) * 2]);
        }
        __syncthreads();
    }

    // -------- epilogue --------
    int crow0 = m0 + wm + (lane >> 2);
    int ccol0 = n0 + wn + (lane & 3) * 2;
    #pragma unroll
    for (int mt = 0; mt < 2; mt++) {
        #pragma unroll
        for (int half = 0; half < 2; half++) {
            int row = crow0 + mt * 16 + half * 8;
            #pragma unroll
            for (int nt = 0; nt < 8; nt++) {
                int col = ccol0 + nt * 8;
                float f0 = acc[mt][nt][half * 2]     + bias[col];
                float f1 = acc[mt][nt][half * 2 + 1] + bias[col + 1];
                if (MODE == 0) {
                    uint32_t pk;
                    asm("cvt.rn.bf16x2.f32 %0, %1, %2;" : "=r"(pk) : "f"(f1), "f"(f0));
                    *(uint32_t*)((__nv_bfloat16*)Cout + (size_t)row * DIM_ + col) = pk;
                } else {
                    const float* qr = resid + (size_t)row * DIM_ + col;
                    float2 o;
                    o.x = qr[0] + gamma[col]     * f0;
                    o.y = qr[1] + gamma[col + 1] * f1;
                    *(float2*)((float*)Cout + (size_t)row * DIM_ + col) = o;
                }
            }
        }
    }
}

// ---------------- 3) offset/aw projection + softmax + locations (64 rows/CTA) ------
__global__ __launch_bounds__(256) void offaw_kernel(
    const float* __restrict__ refp,
    const float* __restrict__ offw, const float* __restrict__ offb,
    const float* __restrict__ aww,  const float* __restrict__ awb)
{
    __shared__ float As[16][64];
    __shared__ float Bs[16][72];
    __shared__ float Ls[64][73];

    int tid = threadIdx.x;
    int by = blockIdx.x;
    int tx = tid & 7;
    int ty = tid >> 3;
    float acc[2][9] = {};
    const float* Ab = g_qn + (size_t)by * 64 * DIM_;

    for (int k0 = 0; k0 < DIM_; k0 += 16) {
        {
            int r = tid >> 2, c4 = (tid & 3) * 4;
            float4 v = *(const float4*)(Ab + (size_t)r * DIM_ + k0 + c4);
            As[c4 + 0][r] = v.x; As[c4 + 1][r] = v.y;
            As[c4 + 2][r] = v.z; As[c4 + 3][r] = v.w;
        }
        for (int idx = tid; idx < 16 * 72; idx += 256) {
            int r = idx / 72, c = idx % 72;
            Bs[r][c] = (c < 48) ? offw[(size_t)(k0 + r) * 48 + c]
                                : aww[(size_t)(k0 + r) * 24 + (c - 48)];
        }
        __syncthreads();
        #pragma unroll
        for (int k = 0; k < 16; k++) {
            float a[2], bb[9];
            a[0] = As[k][ty * 2]; a[1] = As[k][ty * 2 + 1];
            #pragma unroll
            for (int j = 0; j < 9; j++) bb[j] = Bs[k][tx * 9 + j];
            #pragma unroll
            for (int i = 0; i < 2; i++)
                #pragma unroll
                for (int j = 0; j < 9; j++)
                    acc[i][j] = fmaf(a[i], bb[j], acc[i][j]);
        }
        __syncthreads();
    }
    #pragma unroll
    for (int i = 0; i < 2; i++)
        #pragma unroll
        for (int j = 0; j < 9; j++) {
            int c = tx * 9 + j;
            float bias = (c < 48) ? offb[c] : awb[c - 48];
            Ls[ty * 2 + i][c] = acc[i][j] + bias;
        }
    __syncthreads();

    int warp = tid >> 5, lane = tid & 31;
    for (int r = warp; r < 64; r += 8) {
        int qi = by * 64 + r;
        float x = (lane < 24) ? Ls[r][48 + lane] : -1e30f;
        float m = x;
        #pragma unroll
        for (int o = 16; o; o >>= 1) m = fmaxf(m, __shfl_xor_sync(0xffffffffu, m, o));
        float e = (lane < 24) ? __expf(x - m) : 0.f;
        float ssum = e;
        #pragma unroll
        for (int o = 16; o; o >>= 1) ssum += __shfl_xor_sync(0xffffffffu, ssum, o);
        if (lane < 24) g_aw[(size_t)qi * 24 + lane] = e / ssum;
        float rx = refp[(size_t)qi * 2 + 0];
        float ry = refp[(size_t)qi * 2 + 1];
        for (int j = lane; j < 48; j += 32) {
            float ref = (j & 1) ? ry : rx;
            g_loc[(size_t)qi * 48 + j] = ref + Ls[r][j] * (1.f / 64.f);
        }
    }
}

// ---------------- 4) bilinear sampling (bf16 value -> bf16 attn) ----------------
__global__ __launch_bounds__(256) void sample_kernel()
{
    int w = blockIdx.x * 8 + (threadIdx.x >> 5);
    int lane = threadIdx.x & 31;
    int h  = w % HEADS_;
    int qi = w / HEADS_;
    int b  = qi >> 12;
    float a0 = 0.f, a1 = 0.f, a2 = 0.f, a3 = 0.f;
    const __nv_bfloat16* val = g_valb + (size_t)b * NQ_ * DIM_ + h * HD_;
    #pragma unroll
    for (int p = 0; p < POINTS_; p++) {
        float lx = g_loc[(size_t)qi * 48 + (h * POINTS_ + p) * 2 + 0];
        float ly = g_loc[(size_t)qi * 48 + (h * POINTS_ + p) * 2 + 1];
        float aw = g_aw[(size_t)qi * 24 + h * POINTS_ + p];
        float xf = lx * HW_ - 0.5f;
        float yf = ly * HW_ - 0.5f;
        float x0f = floorf(xf), y0f = floorf(yf);
        float wx = xf - x0f, wy = yf - y0f;
        int x0 = (int)x0f, y0 = (int)y0f;
        #pragma unroll
        for (int dy = 0; dy < 2; dy++) {
            #pragma unroll
            for (int dx = 0; dx < 2; dx++) {
                int xi = x0 + dx, yi = y0 + dy;
                if (xi < 0 || xi >= HW_ || yi < 0 || yi >= HW_) continue;
                float cw = aw * (dy ? wy : 1.f - wy) * (dx ? wx : 1.f - wx);
                const __nv_bfloat16* vv = val + (size_t)(yi * HW_ + xi) * DIM_;
                a0 = fmaf(cw, __bfloat162float(vv[lane]),      a0);
                a1 = fmaf(cw, __bfloat162float(vv[lane + 32]), a1);
                a2 = fmaf(cw, __bfloat162float(vv[lane + 64]), a2);
                a3 = fmaf(cw, __bfloat162float(vv[lane + 96]), a3);
            }
        }
    }
    __nv_bfloat16* o = g_attnb + (size_t)qi * DIM_ + h * HD_;
    o[lane]      = __float2bfloat16(a0);
    o[lane + 32] = __float2bfloat16(a1);
    o[lane + 64] = __float2bfloat16(a2);
    o[lane + 96] = __float2bfloat16(a3);
}

// ---------------- launch ----------------
extern "C" void kernel_launch(void* const* d_in, const int* in_sizes, int n_in,
                              void* d_out, int out_size)
{
    const float* query = (const float*)d_in[0];
    const float* refp  = (const float*)d_in[1];
    const float* feat  = (const float*)d_in[2];
    const float* lnw   = (const float*)d_in[5];
    const float* lnb   = (const float*)d_in[6];
    const float* vpw   = (const float*)d_in[7];
    const float* vpb   = (const float*)d_in[8];
    const float* offw  = (const float*)d_in[9];
    const float* offb  = (const float*)d_in[10];
    const float* aww   = (const float*)d_in[11];
    const float* awb   = (const float*)d_in[12];
    const float* outw  = (const float*)d_in[13];
    const float* outb  = (const float*)d_in[14];
    const float* gamma = (const float*)d_in[15];
    float* out = (float*)d_out;

    __nv_bfloat16 *p_featb, *p_valb, *p_attnb, *p_vpwt, *p_outwt;
    cudaGetSymbolAddress((void**)&p_featb, g_featb);
    cudaGetSymbolAddress((void**)&p_valb,  g_valb);
    cudaGetSymbolAddress((void**)&p_attnb, g_attnb);
    cudaGetSymbolAddress((void**)&p_vpwt,  g_vpwt);
    cudaGetSymbolAddress((void**)&p_outwt, g_outwt);

    const int SMEM = 4 * STAGE_B;   // 81920
    cudaFuncSetAttribute(gemm_bf16<0>, cudaFuncAttributeMaxDynamicSharedMemorySize, SMEM);
    cudaFuncSetAttribute(gemm_bf16<1>, cudaFuncAttributeMaxDynamicSharedMemorySize, SMEM);

    dim3 gg(DIM_ / 128, NROWS_ / 128);   // (6, 64)
    dim3 tg(DIM_ / 32, DIM_ / 32);       // (24, 24)
    int n4 = NROWS_ * DIM_ / 4;

    ln_kernel<<<NROWS_, 256>>>(query, lnw, lnb);
    convA_kernel<<<(n4 + 255) / 256, 256>>>((const float4*)feat, (uint2*)p_featb, n4);
    convT_kernel<<<tg, dim3(32, 8)>>>(vpw, p_vpwt);
    convT_kernel<<<tg, dim3(32, 8)>>>(outw, p_outwt);
    gemm_bf16<0><<<gg, 256, SMEM>>>(p_featb, p_vpwt, vpb, p_valb, nullptr, nullptr);
    offaw_kernel<<<NROWS_ / 64, 256>>>(refp, offw, offb, aww, awb);
    sample_kernel<<<NROWS_ * HEADS_ / 8, 256>>>();
    gemm_bf16<1><<<gg, 256, SMEM>>>(p_attnb, p_outwt, outb, out, query, gamma);
}

// round 4
// speedup vs baseline: 2.7434x; 1.4664x over previous
#include <cuda_runtime.h>
#include <cuda_bf16.h>
#include <math.h>
#include <cstdint>

#define BS_    2
#define NQ_    4096
#define DIM_   768
#define HEADS_ 6
#define POINTS_ 4
#define HD_    128
#define HW_    64
#define NROWS_ (BS_*NQ_)   // 8192

// ---------------- scratch (no allocations allowed) ----------------
__device__ __align__(128) __nv_bfloat16 g_qnb  [NROWS_*DIM_];   // layernormed query (bf16)
__device__ __align__(128) __nv_bfloat16 g_featb[NROWS_*DIM_];
__device__ __align__(128) __nv_bfloat16 g_valb [NROWS_*DIM_];
__device__ __align__(128) __nv_bfloat16 g_attnb[NROWS_*DIM_];
__device__ __align__(128) __nv_bfloat16 g_vpwt [DIM_*DIM_];     // vp_w^T  [N,K]
__device__ __align__(128) __nv_bfloat16 g_outwt[DIM_*DIM_];     // out_w^T [N,K]
__device__ __align__(128) float g_loc [NROWS_*HEADS_*POINTS_*2];
__device__ __align__(128) float g_aw  [NROWS_*HEADS_*POINTS_];

// ================= PTX helpers =================
__device__ __forceinline__ uint32_t smem_u32(const void* p) {
    uint32_t a;
    asm("{ .reg .u64 t; cvta.to.shared.u64 t, %1; cvt.u32.u64 %0, t; }" : "=r"(a) : "l"(p));
    return a;
}
__device__ __forceinline__ void cp16(uint32_t dst, const void* src) {
    asm volatile("cp.async.cg.shared.global [%0], [%1], 16;" :: "r"(dst), "l"(src));
}
#define CP_COMMIT() asm volatile("cp.async.commit_group;" ::: "memory")

__device__ __forceinline__ void ldsm4(uint32_t& r0, uint32_t& r1, uint32_t& r2, uint32_t& r3,
                                      uint32_t addr) {
    asm volatile("ldmatrix.sync.aligned.m8n8.x4.shared.b16 {%0,%1,%2,%3}, [%4];"
                 : "=r"(r0), "=r"(r1), "=r"(r2), "=r"(r3) : "r"(addr));
}
__device__ __forceinline__ void mma_bf16(float* c, const uint32_t* a, const uint32_t* b) {
    asm volatile("mma.sync.aligned.m16n8k16.row.col.f32.bf16.bf16.f32 "
                 "{%0,%1,%2,%3}, {%4,%5,%6,%7}, {%8,%9}, {%0,%1,%2,%3};"
                 : "+f"(c[0]), "+f"(c[1]), "+f"(c[2]), "+f"(c[3])
                 : "r"(a[0]), "r"(a[1]), "r"(a[2]), "r"(a[3]), "r"(b[0]), "r"(b[1]));
}

// ---------------- 1) LayerNorm -> bf16 qn (384 threads, float2 per thread) ---------
__global__ __launch_bounds__(384) void ln_kernel(
    const float* __restrict__ query,
    const float* __restrict__ w, const float* __restrict__ b)
{
    int row = blockIdx.x;
    int tid = threadIdx.x;
    const float2* x = (const float2*)(query + (size_t)row * DIM_);
    float2 v = x[tid];
    float s = v.x + v.y;
    __shared__ float red[12];
    __shared__ float red2[12];
    #pragma unroll
    for (int o = 16; o; o >>= 1) s += __shfl_xor_sync(0xffffffffu, s, o);
    if ((tid & 31) == 0) red[tid >> 5] = s;
    __syncthreads();
    if (tid < 32) {
        float t = (tid < 12) ? red[tid] : 0.f;
        #pragma unroll
        for (int o = 8; o; o >>= 1) t += __shfl_xor_sync(0xffffffffu, t, o);
        if (tid == 0) red[0] = t;
    }
    __syncthreads();
    float mean = red[0] * (1.f / DIM_);
    float d0 = v.x - mean, d1 = v.y - mean;
    s = d0 * d0 + d1 * d1;
    #pragma unroll
    for (int o = 16; o; o >>= 1) s += __shfl_xor_sync(0xffffffffu, s, o);
    if ((tid & 31) == 0) red2[tid >> 5] = s;
    __syncthreads();
    if (tid < 32) {
        float t = (tid < 12) ? red2[tid] : 0.f;
        #pragma unroll
        for (int o = 8; o; o >>= 1) t += __shfl_xor_sync(0xffffffffu, t, o);
        if (tid == 0) red2[0] = t;
    }
    __syncthreads();
    float rstd = rsqrtf(red2[0] * (1.f / DIM_) + 1e-6f);
    float2 ww = ((const float2*)w)[tid];
    float2 bb = ((const float2*)b)[tid];
    float o0 = d0 * rstd * ww.x + bb.x;
    float o1 = d1 * rstd * ww.y + bb.y;
    uint32_t pk;
    asm("cvt.rn.bf16x2.f32 %0, %1, %2;" : "=r"(pk) : "f"(o1), "f"(o0));
    ((uint32_t*)(g_qnb + (size_t)row * DIM_))[tid] = pk;
}

// ---------------- fp32 -> bf16 convert ----------------
__global__ __launch_bounds__(256) void convA_kernel(
    const float4* __restrict__ in, uint2* __restrict__ out, int n4)
{
    int i = blockIdx.x * 256 + threadIdx.x;
    if (i >= n4) return;
    float4 v = in[i];
    uint32_t lo, hi;
    asm("cvt.rn.bf16x2.f32 %0, %1, %2;" : "=r"(lo) : "f"(v.y), "f"(v.x));
    asm("cvt.rn.bf16x2.f32 %0, %1, %2;" : "=r"(hi) : "f"(v.w), "f"(v.z));
    out[i] = make_uint2(lo, hi);
}

// ---------------- transpose + convert weights (both in one launch, grid.z) --------
__global__ __launch_bounds__(256) void convT_kernel(
    const float* __restrict__ W0, __nv_bfloat16* __restrict__ Wt0,
    const float* __restrict__ W1, __nv_bfloat16* __restrict__ Wt1)
{
    const float* W        = blockIdx.z ? W1  : W0;
    __nv_bfloat16* Wt     = blockIdx.z ? Wt1 : Wt0;
    __shared__ float t[32][33];
    int bx = blockIdx.x * 32, by = blockIdx.y * 32;
    int tx = threadIdx.x, ty = threadIdx.y;
    #pragma unroll
    for (int i = 0; i < 32; i += 8)
        t[ty + i][tx] = W[(size_t)(by + ty + i) * DIM_ + bx + tx];
    __syncthreads();
    #pragma unroll
    for (int i = 0; i < 32; i += 8)
        Wt[(size_t)(bx + ty + i) * DIM_ + by + tx] = __float2bfloat16(t[tx][ty + i]);
}

// ---------------- HMMA bf16 GEMM: C[8192x768] = A @ Bt^T --------------------------
#define KC       32
#define RSB      80              // row stride bytes (32 bf16 + 8 pad)
#define STAGE_B  (2 * 128 * RSB) // 20480
#define NSTEP    (DIM_ / KC)     // 24

template <int MODE>
__global__ __launch_bounds__(256, 2) void gemm_bf16(
    const __nv_bfloat16* __restrict__ A, const __nv_bfloat16* __restrict__ Bt,
    const float* __restrict__ bias, void* __restrict__ Cout,
    const float* __restrict__ resid, const float* __restrict__ gamma)
{
    extern __shared__ __align__(128) char dsm[];
    uint32_t sb = smem_u32(dsm);
    int tid = threadIdx.x, wid = tid >> 5, lane = tid & 31;
    int n0 = blockIdx.x * 128, m0 = blockIdx.y * 128;
    int wm = (wid & 3) * 32;
    int wn = (wid >> 2) * 64;

    int lrow[2], lc[2];
    #pragma unroll
    for (int j = 0; j < 2; j++) {
        int id = j * 256 + tid;
        lrow[j] = id >> 2;
        lc[j]   = (id & 3) * 8;
    }

    auto load_stage = [&](int s) {
        uint32_t base = sb + (s & 3) * STAGE_B;
        int k0 = s * KC;
        #pragma unroll
        for (int j = 0; j < 2; j++)
            cp16(base + lrow[j] * RSB + lc[j] * 2,
                 A + (size_t)(m0 + lrow[j]) * DIM_ + k0 + lc[j]);
        #pragma unroll
        for (int j = 0; j < 2; j++)
            cp16(base + 128 * RSB + lrow[j] * RSB + lc[j] * 2,
                 Bt + (size_t)(n0 + lrow[j]) * DIM_ + k0 + lc[j]);
        CP_COMMIT();
    };

    float acc[2][8][4] = {};

    load_stage(0); load_stage(1); load_stage(2);

    for (int s = 0; s < NSTEP; s++) {
        // wait for stage s, barrier, then prefetch into the buffer freed at s-1
        if (s + 3 < NSTEP) {
            asm volatile("cp.async.wait_group 2;" ::: "memory");
            __syncthreads();
            load_stage(s + 3);
        } else if (s + 3 == NSTEP) {
            asm volatile("cp.async.wait_group 2;" ::: "memory");
            __syncthreads();
        } else if (s + 2 == NSTEP) {
            asm volatile("cp.async.wait_group 1;" ::: "memory");
            __syncthreads();
        } else {
            asm volatile("cp.async.wait_group 0;" ::: "memory");
            __syncthreads();
        }

        uint32_t abase = sb + (s & 3) * STAGE_B;
        uint32_t bbase = abase + 128 * RSB;
        #pragma unroll
        for (int kk = 0; kk < 2; kk++) {
            uint32_t af[2][4], bf[4][4];
            #pragma unroll
            for (int mt = 0; mt < 2; mt++) {
                int r  = wm + mt * 16 + (lane & 15);
                int kc = kk * 16 + (lane >> 4) * 8;
                ldsm4(af[mt][0], af[mt][1], af[mt][2], af[mt][3],
                      abase + r * RSB + kc * 2);
            }
            #pragma unroll
            for (int np = 0; np < 4; np++) {
                int n  = wn + np * 16 + (lane & 7) + ((lane >> 4) << 3);
                int kc = kk * 16 + ((lane >> 3) & 1) * 8;
                ldsm4(bf[np][0], bf[np][1], bf[np][2], bf[np][3],
                      bbase + n * RSB + kc * 2);
            }
            #pragma unroll
            for (int mt = 0; mt < 2; mt++)
                #pragma unroll
                for (int nt = 0; nt < 8; nt++)
                    mma_bf16(acc[mt][nt], af[mt], &bf[nt >> 1][(nt & 1) * 2]);
        }
    }

    // -------- epilogue (stores are full 32B sectors; no staging needed) --------
    int crow0 = m0 + wm + (lane >> 2);
    int ccol0 = n0 + wn + (lane & 3) * 2;
    #pragma unroll
    for (int mt = 0; mt < 2; mt++) {
        #pragma unroll
        for (int half = 0; half < 2; half++) {
            int row = crow0 + mt * 16 + half * 8;
            #pragma unroll
            for (int nt = 0; nt < 8; nt++) {
                int col = ccol0 + nt * 8;
                float f0 = acc[mt][nt][half * 2]     + bias[col];
                float f1 = acc[mt][nt][half * 2 + 1] + bias[col + 1];
                if (MODE == 0) {
                    uint32_t pk;
                    asm("cvt.rn.bf16x2.f32 %0, %1, %2;" : "=r"(pk) : "f"(f1), "f"(f0));
                    *(uint32_t*)((__nv_bfloat16*)Cout + (size_t)row * DIM_ + col) = pk;
                } else {
                    const float* qr = resid + (size_t)row * DIM_ + col;
                    float2 o;
                    o.x = qr[0] + gamma[col]     * f0;
                    o.y = qr[1] + gamma[col + 1] * f1;
                    *(float2*)((float*)Cout + (size_t)row * DIM_ + col) = o;
                }
            }
        }
    }
}

// ---------------- 3) offset/aw projection + softmax + locations (bf16 input) ------
__global__ __launch_bounds__(256) void offaw_kernel(
    const float* __restrict__ refp,
    const float* __restrict__ offw, const float* __restrict__ offb,
    const float* __restrict__ aww,  const float* __restrict__ awb)
{
    __shared__ float As[16][64];
    __shared__ float Bs[16][72];
    __shared__ float Ls[64][73];

    int tid = threadIdx.x;
    int by = blockIdx.x;
    int tx = tid & 7;
    int ty = tid >> 3;
    float acc[2][9] = {};
    const __nv_bfloat16* Ab = g_qnb + (size_t)by * 64 * DIM_;

    for (int k0 = 0; k0 < DIM_; k0 += 16) {
        {
            int r = tid >> 2, c4 = (tid & 3) * 4;
            uint2 raw = *(const uint2*)(Ab + (size_t)r * DIM_ + k0 + c4);
            float2 p0 = __bfloat1622float2(*(__nv_bfloat162*)&raw.x);
            float2 p1 = __bfloat1622float2(*(__nv_bfloat162*)&raw.y);
            As[c4 + 0][r] = p0.x; As[c4 + 1][r] = p0.y;
            As[c4 + 2][r] = p1.x; As[c4 + 3][r] = p1.y;
        }
        for (int idx = tid; idx < 16 * 72; idx += 256) {
            int r = idx / 72, c = idx % 72;
            Bs[r][c] = (c < 48) ? offw[(size_t)(k0 + r) * 48 + c]
                                : aww[(size_t)(k0 + r) * 24 + (c - 48)];
        }
        __syncthreads();
        #pragma unroll
        for (int k = 0; k < 16; k++) {
            float a[2], bb[9];
            a[0] = As[k][ty * 2]; a[1] = As[k][ty * 2 + 1];
            #pragma unroll
            for (int j = 0; j < 9; j++) bb[j] = Bs[k][tx * 9 + j];
            #pragma unroll
            for (int i = 0; i < 2; i++)
                #pragma unroll
                for (int j = 0; j < 9; j++)
                    acc[i][j] = fmaf(a[i], bb[j], acc[i][j]);
        }
        __syncthreads();
    }
    #pragma unroll
    for (int i = 0; i < 2; i++)
        #pragma unroll
        for (int j = 0; j < 9; j++) {
            int c = tx * 9 + j;
            float bias = (c < 48) ? offb[c] : awb[c - 48];
            Ls[ty * 2 + i][c] = acc[i][j] + bias;
        }
    __syncthreads();

    int warp = tid >> 5, lane = tid & 31;
    for (int r = warp; r < 64; r += 8) {
        int qi = by * 64 + r;
        float x = (lane < 24) ? Ls[r][48 + lane] : -1e30f;
        float m = x;
        #pragma unroll
        for (int o = 16; o; o >>= 1) m = fmaxf(m, __shfl_xor_sync(0xffffffffu, m, o));
        float e = (lane < 24) ? __expf(x - m) : 0.f;
        float ssum = e;
        #pragma unroll
        for (int o = 16; o; o >>= 1) ssum += __shfl_xor_sync(0xffffffffu, ssum, o);
        if (lane < 24) g_aw[(size_t)qi * 24 + lane] = e / ssum;
        float rx = refp[(size_t)qi * 2 + 0];
        float ry = refp[(size_t)qi * 2 + 1];
        for (int j = lane; j < 48; j += 32) {
            float ref = (j & 1) ? ry : rx;
            g_loc[(size_t)qi * 48 + j] = ref + Ls[r][j] * (1.f / 64.f);
        }
    }
}

// ---------------- 4) bilinear sampling (bf16x2 vectorized) ----------------
__global__ __launch_bounds__(256) void sample_kernel()
{
    int w = blockIdx.x * 8 + (threadIdx.x >> 5);
    int lane = threadIdx.x & 31;
    int h  = w % HEADS_;
    int qi = w / HEADS_;
    int b  = qi >> 12;
    float a0 = 0.f, a1 = 0.f, a2 = 0.f, a3 = 0.f;
    const __nv_bfloat162* val2 =
        (const __nv_bfloat162*)(g_valb + (size_t)b * NQ_ * DIM_ + h * HD_);
    #pragma unroll
    for (int p = 0; p < POINTS_; p++) {
        float lx = g_loc[(size_t)qi * 48 + (h * POINTS_ + p) * 2 + 0];
        float ly = g_loc[(size_t)qi * 48 + (h * POINTS_ + p) * 2 + 1];
        float aw = g_aw[(size_t)qi * 24 + h * POINTS_ + p];
        float xf = lx * HW_ - 0.5f;
        float yf = ly * HW_ - 0.5f;
        float x0f = floorf(xf), y0f = floorf(yf);
        float wx = xf - x0f, wy = yf - y0f;
        int x0 = (int)x0f, y0 = (int)y0f;
        #pragma unroll
        for (int dy = 0; dy < 2; dy++) {
            #pragma unroll
            for (int dx = 0; dx < 2; dx++) {
                int xi = x0 + dx, yi = y0 + dy;
                if (xi < 0 || xi >= HW_ || yi < 0 || yi >= HW_) continue;
                float cw = aw * (dy ? wy : 1.f - wy) * (dx ? wx : 1.f - wx);
                const __nv_bfloat162* vv = val2 + (size_t)(yi * HW_ + xi) * (DIM_ / 2);
                float2 f0 = __bfloat1622float2(vv[lane]);
                float2 f1 = __bfloat1622float2(vv[lane + 32]);
                a0 = fmaf(cw, f0.x, a0);
                a1 = fmaf(cw, f0.y, a1);
                a2 = fmaf(cw, f1.x, a2);
                a3 = fmaf(cw, f1.y, a3);
            }
        }
    }
    __nv_bfloat162* o2 = (__nv_bfloat162*)(g_attnb + (size_t)qi * DIM_ + h * HD_);
    o2[lane]      = __floats2bfloat162_rn(a0, a1);
    o2[lane + 32] = __floats2bfloat162_rn(a2, a3);
}

// ---------------- launch ----------------
extern "C" void kernel_launch(void* const* d_in, const int* in_sizes, int n_in,
                              void* d_out, int out_size)
{
    const float* query = (const float*)d_in[0];
    const float* refp  = (const float*)d_in[1];
    const float* feat  = (const float*)d_in[2];
    const float* lnw   = (const float*)d_in[5];
    const float* lnb   = (const float*)d_in[6];
    const float* vpw   = (const float*)d_in[7];
    const float* vpb   = (const float*)d_in[8];
    const float* offw  = (const float*)d_in[9];
    const float* offb  = (const float*)d_in[10];
    const float* aww   = (const float*)d_in[11];
    const float* awb   = (const float*)d_in[12];
    const float* outw  = (const float*)d_in[13];
    const float* outb  = (const float*)d_in[14];
    const float* gamma = (const float*)d_in[15];
    float* out = (float*)d_out;

    __nv_bfloat16 *p_featb, *p_valb, *p_attnb, *p_vpwt, *p_outwt;
    cudaGetSymbolAddress((void**)&p_featb, g_featb);
    cudaGetSymbolAddress((void**)&p_valb,  g_valb);
    cudaGetSymbolAddress((void**)&p_attnb, g_attnb);
    cudaGetSymbolAddress((void**)&p_vpwt,  g_vpwt);
    cudaGetSymbolAddress((void**)&p_outwt, g_outwt);

    const int SMEM = 4 * STAGE_B;   // 81920
    cudaFuncSetAttribute(gemm_bf16<0>, cudaFuncAttributeMaxDynamicSharedMemorySize, SMEM);
    cudaFuncSetAttribute(gemm_bf16<1>, cudaFuncAttributeMaxDynamicSharedMemorySize, SMEM);

    dim3 gg(DIM_ / 128, NROWS_ / 128);      // (6, 64)
    dim3 tg(DIM_ / 32, DIM_ / 32, 2);       // (24, 24, 2)
    int n4 = NROWS_ * DIM_ / 4;

    ln_kernel<<<NROWS_, 384>>>(query, lnw, lnb);
    convA_kernel<<<(n4 + 255) / 256, 256>>>((const float4*)feat, (uint2*)p_featb, n4);
    convT_kernel<<<tg, dim3(32, 8)>>>(vpw, p_vpwt, outw, p_outwt);
    gemm_bf16<0><<<gg, 256, SMEM>>>(p_featb, p_vpwt, vpb, p_valb, nullptr, nullptr);
    offaw_kernel<<<NROWS_ / 64, 256>>>(refp, offw, offb, aww, awb);
    sample_kernel<<<NROWS_ * HEADS_ / 8, 256>>>();
    gemm_bf16<1><<<gg, 256, SMEM>>>(p_attnb, p_outwt, outb, out, query, gamma);
}

// round 7
// speedup vs baseline: 5.0263x; 1.8321x over previous
#include <cuda_runtime.h>
#include <cuda_bf16.h>
#include <math.h>
#include <cstdint>

#define BS_    2
#define NQ_    4096
#define DIM_   768
#define HEADS_ 6
#define POINTS_ 4
#define HD_    128
#define HW_    64
#define NROWS_ (BS_*NQ_)   // 8192
#define NCAT   96          // padded offset/aw projection width (72 -> 96)

// ---------------- scratch ----------------
__device__ __align__(128) __nv_bfloat16 g_qnb  [NROWS_*DIM_];
__device__ __align__(128) __nv_bfloat16 g_featb[NROWS_*DIM_];
__device__ __align__(128) __nv_bfloat16 g_valb [NROWS_*DIM_];
__device__ __align__(128) __nv_bfloat16 g_attnb[NROWS_*DIM_];
__device__ __align__(128) __nv_bfloat16 g_vpwt [DIM_*DIM_];
__device__ __align__(128) __nv_bfloat16 g_outwt[DIM_*DIM_];
__device__ __align__(128) __nv_bfloat16 g_catwt[NCAT*DIM_];   // concat(off,aw)^T padded
__device__ __align__(128) float g_bcat[NCAT];
__device__ __align__(128) float g_logits[NROWS_*NCAT];
__device__ __align__(128) float g_loc [NROWS_*HEADS_*POINTS_*2];
__device__ __align__(128) float g_aw  [NROWS_*HEADS_*POINTS_];

// ================= PTX helpers =================
__device__ __forceinline__ uint32_t smem_u32(const void* p) {
    uint32_t a;
    asm("{ .reg .u64 t; cvta.to.shared.u64 t, %1; cvt.u32.u64 %0, t; }" : "=r"(a) : "l"(p));
    return a;
}
__device__ __forceinline__ void cp16(uint32_t dst, const void* src) {
    asm volatile("cp.async.cg.shared.global [%0], [%1], 16;" :: "r"(dst), "l"(src));
}
#define CP_COMMIT() asm volatile("cp.async.commit_group;" ::: "memory")

__device__ __forceinline__ void ldsm4(uint32_t& r0, uint32_t& r1, uint32_t& r2, uint32_t& r3,
                                      uint32_t addr) {
    asm volatile("ldmatrix.sync.aligned.m8n8.x4.shared.b16 {%0,%1,%2,%3}, [%4];"
                 : "=r"(r0), "=r"(r1), "=r"(r2), "=r"(r3) : "r"(addr));
}
__device__ __forceinline__ void mma_bf16(float* c, const uint32_t* a, const uint32_t* b) {
    asm volatile("mma.sync.aligned.m16n8k16.row.col.f32.bf16.bf16.f32 "
                 "{%0,%1,%2,%3}, {%4,%5,%6,%7}, {%8,%9}, {%0,%1,%2,%3};"
                 : "+f"(c[0]), "+f"(c[1]), "+f"(c[2]), "+f"(c[3])
                 : "r"(a[0]), "r"(a[1]), "r"(a[2]), "r"(a[3]), "r"(b[0]), "r"(b[1]));
}

// ---------------- 1) LayerNorm -> bf16 qn ----------------
__global__ __launch_bounds__(384) void ln_kernel(
    const float* __restrict__ query,
    const float* __restrict__ w, const float* __restrict__ b)
{
    int row = blockIdx.x;
    int tid = threadIdx.x;
    const float2* x = (const float2*)(query + (size_t)row * DIM_);
    float2 v = x[tid];
    float s = v.x + v.y;
    __shared__ float red[12];
    __shared__ float red2[12];
    #pragma unroll
    for (int o = 16; o; o >>= 1) s += __shfl_xor_sync(0xffffffffu, s, o);
    if ((tid & 31) == 0) red[tid >> 5] = s;
    __syncthreads();
    if (tid < 32) {
        float t = (tid < 12) ? red[tid] : 0.f;
        #pragma unroll
        for (int o = 8; o; o >>= 1) t += __shfl_xor_sync(0xffffffffu, t, o);
        if (tid == 0) red[0] = t;
    }
    __syncthreads();
    float mean = red[0] * (1.f / DIM_);
    float d0 = v.x - mean, d1 = v.y - mean;
    s = d0 * d0 + d1 * d1;
    #pragma unroll
    for (int o = 16; o; o >>= 1) s += __shfl_xor_sync(0xffffffffu, s, o);
    if ((tid & 31) == 0) red2[tid >> 5] = s;
    __syncthreads();
    if (tid < 32) {
        float t = (tid < 12) ? red2[tid] : 0.f;
        #pragma unroll
        for (int o = 8; o; o >>= 1) t += __shfl_xor_sync(0xffffffffu, t, o);
        if (tid == 0) red2[0] = t;
    }
    __syncthreads();
    float rstd = rsqrtf(red2[0] * (1.f / DIM_) + 1e-6f);
    float2 ww = ((const float2*)w)[tid];
    float2 bb = ((const float2*)b)[tid];
    float o0 = d0 * rstd * ww.x + bb.x;
    float o1 = d1 * rstd * ww.y + bb.y;
    uint32_t pk;
    asm("cvt.rn.bf16x2.f32 %0, %1, %2;" : "=r"(pk) : "f"(o1), "f"(o0));
    ((uint32_t*)(g_qnb + (size_t)row * DIM_))[tid] = pk;
}

// ---------------- fp32 -> bf16 convert ----------------
__global__ __launch_bounds__(256) void convA_kernel(
    const float4* __restrict__ in, uint2* __restrict__ out, int n4)
{
    int i = blockIdx.x * 256 + threadIdx.x;
    if (i >= n4) return;
    float4 v = in[i];
    uint32_t lo, hi;
    asm("cvt.rn.bf16x2.f32 %0, %1, %2;" : "=r"(lo) : "f"(v.y), "f"(v.x));
    asm("cvt.rn.bf16x2.f32 %0, %1, %2;" : "=r"(hi) : "f"(v.w), "f"(v.z));
    out[i] = make_uint2(lo, hi);
}

// ---------------- transpose + convert weights ----------------
__global__ __launch_bounds__(256) void convT_kernel(
    const float* __restrict__ W0, __nv_bfloat16* __restrict__ Wt0,
    const float* __restrict__ W1, __nv_bfloat16* __restrict__ Wt1)
{
    const float* W        = blockIdx.z ? W1  : W0;
    __nv_bfloat16* Wt     = blockIdx.z ? Wt1 : Wt0;
    __shared__ float t[32][33];
    int bx = blockIdx.x * 32, by = blockIdx.y * 32;
    int tx = threadIdx.x, ty = threadIdx.y;
    #pragma unroll
    for (int i = 0; i < 32; i += 8)
        t[ty + i][tx] = W[(size_t)(by + ty + i) * DIM_ + bx + tx];
    __syncthreads();
    #pragma unroll
    for (int i = 0; i < 32; i += 8)
        Wt[(size_t)(bx + ty + i) * DIM_ + by + tx] = __float2bfloat16(t[tx][ty + i]);
}

// ---------------- concat offset/aw weights -> g_catwt[96][768] + g_bcat ----------
__global__ __launch_bounds__(256) void convW_kernel(
    const float* __restrict__ offw, const float* __restrict__ offb,
    const float* __restrict__ aww,  const float* __restrict__ awb)
{
    int i = blockIdx.x * 256 + threadIdx.x;   // over 96*768
    if (i < NCAT * DIM_) {
        int c = i / DIM_, k = i % DIM_;
        float v = 0.f;
        if (c < 48)      v = offw[(size_t)k * 48 + c];
        else if (c < 72) v = aww[(size_t)k * 24 + (c - 48)];
        g_catwt[i] = __float2bfloat16(v);
    }
    if (blockIdx.x == 0 && threadIdx.x < NCAT) {
        int c = threadIdx.x;
        g_bcat[c] = (c < 48) ? offb[c] : (c < 72 ? awb[c - 48] : 0.f);
    }
}

// ---------------- HMMA bf16 GEMM: C[M x N] = A @ Bt^T, tile 128x96 -----------------
// MODE 0: C = bf16(acc + bias)
// MODE 1: C = fp32(resid + gamma*(acc + bias))
// MODE 2: C = fp32(acc + bias)
#define KC       32
#define RSB      80
#define A_BYTES  (128 * RSB)          // 10240
#define B_BYTES  (96 * RSB)           // 7680
#define STAGE_B  (A_BYTES + B_BYTES)  // 17920
#define NSTEP    (DIM_ / KC)          // 24

template <int MODE>
__global__ __launch_bounds__(256, 2) void gemm_bf16(
    const __nv_bfloat16* __restrict__ A, const __nv_bfloat16* __restrict__ Bt,
    const float* __restrict__ bias, void* __restrict__ Cout, int ldc,
    const float* __restrict__ resid, const float* __restrict__ gamma)
{
    extern __shared__ __align__(128) char dsm[];
    uint32_t sb = smem_u32(dsm);
    int tid = threadIdx.x, wid = tid >> 5, lane = tid & 31;
    int n0 = blockIdx.x * 96, m0 = blockIdx.y * 128;
    int wm = (wid & 3) * 32;
    int wn = (wid >> 2) * 48;

    int arow[2], alc[2];
    #pragma unroll
    for (int j = 0; j < 2; j++) {
        int id = j * 256 + tid;
        arow[j] = id >> 2;
        alc[j]  = (id & 3) * 8;
    }
    int brow0 = tid >> 2,          blc0 = (tid & 3) * 8;
    int brow1 = (256 + tid) >> 2,  blc1 = (tid & 3) * 8;
    bool bj1 = tid < 128;

    auto load_stage = [&](int s) {
        uint32_t base = sb + (s & 3) * STAGE_B;
        int k0 = s * KC;
        #pragma unroll
        for (int j = 0; j < 2; j++)
            cp16(base + arow[j] * RSB + alc[j] * 2,
                 A + (size_t)(m0 + arow[j]) * DIM_ + k0 + alc[j]);
        cp16(base + A_BYTES + brow0 * RSB + blc0 * 2,
             Bt + (size_t)(n0 + brow0) * DIM_ + k0 + blc0);
        if (bj1)
            cp16(base + A_BYTES + brow1 * RSB + blc1 * 2,
                 Bt + (size_t)(n0 + brow1) * DIM_ + k0 + blc1);
        CP_COMMIT();
    };

    float acc[2][6][4] = {};

    load_stage(0); load_stage(1); load_stage(2);

    for (int s = 0; s < NSTEP; s++) {
        if (s + 3 < NSTEP) {
            asm volatile("cp.async.wait_group 2;" ::: "memory");
            __syncthreads();
            load_stage(s + 3);
        } else if (s + 3 == NSTEP) {
            asm volatile("cp.async.wait_group 2;" ::: "memory");
            __syncthreads();
        } else if (s + 2 == NSTEP) {
            asm volatile("cp.async.wait_group 1;" ::: "memory");
            __syncthreads();
        } else {
            asm volatile("cp.async.wait_group 0;" ::: "memory");
            __syncthreads();
        }

        uint32_t abase = sb + (s & 3) * STAGE_B;
        uint32_t bbase = abase + A_BYTES;
        #pragma unroll
        for (int kk = 0; kk < 2; kk++) {
            uint32_t af[2][4], bf[3][4];
            #pragma unroll
            for (int mt = 0; mt < 2; mt++) {
                int r  = wm + mt * 16 + (lane & 15);
                int kc = kk * 16 + (lane >> 4) * 8;
                ldsm4(af[mt][0], af[mt][1], af[mt][2], af[mt][3],
                      abase + r * RSB + kc * 2);
            }
            #pragma unroll
            for (int np = 0; np < 3; np++) {
                int n  = wn + np * 16 + (lane & 7) + ((lane >> 4) << 3);
                int kc = kk * 16 + ((lane >> 3) & 1) * 8;
                ldsm4(bf[np][0], bf[np][1], bf[np][2], bf[np][3],
                      bbase + n * RSB + kc * 2);
            }
            #pragma unroll
            for (int mt = 0; mt < 2; mt++)
                #pragma unroll
                for (int nt = 0; nt < 6; nt++)
                    mma_bf16(acc[mt][nt], af[mt], &bf[nt >> 1][(nt & 1) * 2]);
        }
    }

    int crow0 = m0 + wm + (lane >> 2);
    int ccol0 = n0 + wn + (lane & 3) * 2;
    #pragma unroll
    for (int mt = 0; mt < 2; mt++) {
        #pragma unroll
        for (int half = 0; half < 2; half++) {
            int row = crow0 + mt * 16 + half * 8;
            #pragma unroll
            for (int nt = 0; nt < 6; nt++) {
                int col = ccol0 + nt * 8;
                float f0 = acc[mt][nt][half * 2]     + bias[col];
                float f1 = acc[mt][nt][half * 2 + 1] + bias[col + 1];
                if (MODE == 0) {
                    uint32_t pk;
                    asm("cvt.rn.bf16x2.f32 %0, %1, %2;" : "=r"(pk) : "f"(f1), "f"(f0));
                    *(uint32_t*)((__nv_bfloat16*)Cout + (size_t)row * ldc + col) = pk;
                } else if (MODE == 1) {
                    const float* qr = resid + (size_t)row * ldc + col;
                    float2 o;
                    o.x = qr[0] + gamma[col]     * f0;
                    o.y = qr[1] + gamma[col + 1] * f1;
                    *(float2*)((float*)Cout + (size_t)row * ldc + col) = o;
                } else {
                    float2 o; o.x = f0; o.y = f1;
                    *(float2*)((float*)Cout + (size_t)row * ldc + col) = o;
                }
            }
        }
    }
}

// ---------------- softmax + sampling locations from logits ----------------
__global__ __launch_bounds__(256) void postproc_kernel(const float* __restrict__ refp)
{
    int warp = threadIdx.x >> 5, lane = threadIdx.x & 31;
    int qi = blockIdx.x * 8 + warp;
    const float* lg = g_logits + (size_t)qi * NCAT;
    float x = (lane < 24) ? lg[48 + lane] : -1e30f;
    float m = x;
    #pragma unroll
    for (int o = 16; o; o >>= 1) m = fmaxf(m, __shfl_xor_sync(0xffffffffu, m, o));
    float e = (lane < 24) ? __expf(x - m) : 0.f;
    float ssum = e;
    #pragma unroll
    for (int o = 16; o; o >>= 1) ssum += __shfl_xor_sync(0xffffffffu, ssum, o);
    if (lane < 24) g_aw[(size_t)qi * 24 + lane] = e / ssum;
    float rx = refp[(size_t)qi * 2 + 0];
    float ry = refp[(size_t)qi * 2 + 1];
    #pragma unroll
    for (int j = lane; j < 48; j += 32) {
        float ref = (j & 1) ? ry : rx;
        g_loc[(size_t)qi * 48 + j] = ref + lg[j] * (1.f / 64.f);
    }
}

// ---------------- bilinear sampling ----------------
__global__ __launch_bounds__(256) void sample_kernel()
{
    int w = blockIdx.x * 8 + (threadIdx.x >> 5);
    int lane = threadIdx.x & 31;
    int h  = w % HEADS_;
    int qi = w / HEADS_;
    int b  = qi >> 12;
    float a0 = 0.f, a1 = 0.f, a2 = 0.f, a3 = 0.f;
    const __nv_bfloat162* val2 =
        (const __nv_bfloat162*)(g_valb + (size_t)b * NQ_ * DIM_ + h * HD_);
    #pragma unroll
    for (int p = 0; p < POINTS_; p++) {
        float lx = g_loc[(size_t)qi * 48 + (h * POINTS_ + p) * 2 + 0];
        float ly = g_loc[(size_t)qi * 48 + (h * POINTS_ + p) * 2 + 1];
        float aw = g_aw[(size_t)qi * 24 + h * POINTS_ + p];
        float xf = lx * HW_ - 0.5f;
        float yf = ly * HW_ - 0.5f;
        float x0f = floorf(xf), y0f = floorf(yf);
        float wx = xf - x0f, wy = yf - y0f;
        int x0 = (int)x0f, y0 = (int)y0f;
        #pragma unroll
        for (int dy = 0; dy < 2; dy++) {
            #pragma unroll
            for (int dx = 0; dx < 2; dx++) {
                int xi = x0 + dx, yi = y0 + dy;
                if (xi < 0 || xi >= HW_ || yi < 0 || yi >= HW_) continue;
                float cw = aw * (dy ? wy : 1.f - wy) * (dx ? wx : 1.f - wx);
                const __nv_bfloat162* vv = val2 + (size_t)(yi * HW_ + xi) * (DIM_ / 2);
                float2 f0 = __bfloat1622float2(vv[lane]);
                float2 f1 = __bfloat1622float2(vv[lane + 32]);
                a0 = fmaf(cw, f0.x, a0);
                a1 = fmaf(cw, f0.y, a1);
                a2 = fmaf(cw, f1.x, a2);
                a3 = fmaf(cw, f1.y, a3);
            }
        }
    }
    __nv_bfloat162* o2 = (__nv_bfloat162*)(g_attnb + (size_t)qi * DIM_ + h * HD_);
    o2[lane]      = __floats2bfloat162_rn(a0, a1);
    o2[lane + 32] = __floats2bfloat162_rn(a2, a3);
}

// ---------------- launch ----------------
extern "C" void kernel_launch(void* const* d_in, const int* in_sizes, int n_in,
                              void* d_out, int out_size)
{
    const float* query = (const float*)d_in[0];
    const float* refp  = (const float*)d_in[1];
    const float* feat  = (const float*)d_in[2];
    const float* lnw   = (const float*)d_in[5];
    const float* lnb   = (const float*)d_in[6];
    const float* vpw   = (const float*)d_in[7];
    const float* vpb   = (const float*)d_in[8];
    const float* offw  = (const float*)d_in[9];
    const float* offb  = (const float*)d_in[10];
    const float* aww   = (const float*)d_in[11];
    const float* awb   = (const float*)d_in[12];
    const float* outw  = (const float*)d_in[13];
    const float* outb  = (const float*)d_in[14];
    const float* gamma = (const float*)d_in[15];
    float* out = (float*)d_out;

    __nv_bfloat16 *p_featb, *p_valb, *p_attnb, *p_vpwt, *p_outwt, *p_catwt, *p_qnb;
    float *p_bcat, *p_logits;
    cudaGetSymbolAddress((void**)&p_featb, g_featb);
    cudaGetSymbolAddress((void**)&p_valb,  g_valb);
    cudaGetSymbolAddress((void**)&p_attnb, g_attnb);
    cudaGetSymbolAddress((void**)&p_vpwt,  g_vpwt);
    cudaGetSymbolAddress((void**)&p_outwt, g_outwt);
    cudaGetSymbolAddress((void**)&p_catwt, g_catwt);
    cudaGetSymbolAddress((void**)&p_qnb,   g_qnb);
    cudaGetSymbolAddress((void**)&p_bcat,  g_bcat);
    cudaGetSymbolAddress((void**)&p_logits,g_logits);

    const int SMEM = 4 * STAGE_B;   // 71680
    cudaFuncSetAttribute(gemm_bf16<0>, cudaFuncAttributeMaxDynamicSharedMemorySize, SMEM);
    cudaFuncSetAttribute(gemm_bf16<1>, cudaFuncAttributeMaxDynamicSharedMemorySize, SMEM);
    cudaFuncSetAttribute(gemm_bf16<2>, cudaFuncAttributeMaxDynamicSharedMemorySize, SMEM);

    dim3 gg(DIM_ / 96, NROWS_ / 128);       // (8, 64)
    dim3 gl(1, NROWS_ / 128);               // (1, 64)
    dim3 tg(DIM_ / 32, DIM_ / 32, 2);       // (24, 24, 2)
    int n4 = NROWS_ * DIM_ / 4;
    int ncw = (NCAT * DIM_ + 255) / 256;

    ln_kernel<<<NROWS_, 384>>>(query, lnw, lnb);
    convA_kernel<<<(n4 + 255) / 256, 256>>>((const float4*)feat, (uint2*)p_featb, n4);
    convT_kernel<<<tg, dim3(32, 8)>>>(vpw, p_vpwt, outw, p_outwt);
    convW_kernel<<<ncw, 256>>>(offw, offb, aww, awb);
    gemm_bf16<0><<<gg, 256, SMEM>>>(p_featb, p_vpwt, vpb, p_valb, DIM_, nullptr, nullptr);
    gemm_bf16<2><<<gl, 256, SMEM>>>(p_qnb, p_catwt, p_bcat, p_logits, NCAT, nullptr, nullptr);
    postproc_kernel<<<NROWS_ / 8, 256>>>(refp);
    sample_kernel<<<NROWS_ * HEADS_ / 8, 256>>>();
    gemm_bf16<1><<<gg, 256, SMEM>>>(p_attnb, p_outwt, outb, out, DIM_, query, gamma);
}

// round 8
// speedup vs baseline: 5.2814x; 1.0507x over previous
#include <cuda_runtime.h>
#include <cuda_bf16.h>
#include <math.h>
#include <cstdint>

#define BS_    2
#define NQ_    4096
#define DIM_   768
#define HEADS_ 6
#define POINTS_ 4
#define HD_    128
#define HW_    64
#define NROWS_ (BS_*NQ_)   // 8192
#define NCAT   96

// ---------------- scratch ----------------
__device__ __align__(128) __nv_bfloat16 g_qnb  [NROWS_*DIM_];
__device__ __align__(128) __nv_bfloat16 g_featb[NROWS_*DIM_];
__device__ __align__(128) __nv_bfloat16 g_valb [NROWS_*DIM_];
__device__ __align__(128) __nv_bfloat16 g_attnb[NROWS_*DIM_];
__device__ __align__(128) __nv_bfloat16 g_vpwt [DIM_*DIM_];
__device__ __align__(128) __nv_bfloat16 g_outwt[DIM_*DIM_];
__device__ __align__(128) __nv_bfloat16 g_catwt[NCAT*DIM_];
__device__ __align__(128) float g_bcat[NCAT];
__device__ __align__(128) float g_logits[NROWS_*NCAT];

// ================= PTX helpers =================
__device__ __forceinline__ uint32_t smem_u32(const void* p) {
    uint32_t a;
    asm("{ .reg .u64 t; cvta.to.shared.u64 t, %1; cvt.u32.u64 %0, t; }" : "=r"(a) : "l"(p));
    return a;
}
__device__ __forceinline__ void cp16(uint32_t dst, const void* src) {
    asm volatile("cp.async.cg.shared.global [%0], [%1], 16;" :: "r"(dst), "l"(src));
}
#define CP_COMMIT() asm volatile("cp.async.commit_group;" ::: "memory")

__device__ __forceinline__ void ldsm4(uint32_t& r0, uint32_t& r1, uint32_t& r2, uint32_t& r3,
                                      uint32_t addr) {
    asm volatile("ldmatrix.sync.aligned.m8n8.x4.shared.b16 {%0,%1,%2,%3}, [%4];"
                 : "=r"(r0), "=r"(r1), "=r"(r2), "=r"(r3) : "r"(addr));
}
__device__ __forceinline__ void mma_bf16(float* c, const uint32_t* a, const uint32_t* b) {
    asm volatile("mma.sync.aligned.m16n8k16.row.col.f32.bf16.bf16.f32 "
                 "{%0,%1,%2,%3}, {%4,%5,%6,%7}, {%8,%9}, {%0,%1,%2,%3};"
                 : "+f"(c[0]), "+f"(c[1]), "+f"(c[2]), "+f"(c[3])
                 : "r"(a[0]), "r"(a[1]), "r"(a[2]), "r"(a[3]), "r"(b[0]), "r"(b[1]));
}

// ---------------- fused prologue: ln | convA | convT x2 | convW ----------------
// block ranges (384 threads each):
//   [0, 8192)            layernorm, one row per block
//   [8192, 8192+4096)    feat fp32 -> bf16, 384 float4 per block
//   [12288, 12288+1152)  weight transpose tiles (z = tile/576)
//   [13440, 13440+192)   concat off/aw weights
#define PB_LN   NROWS_
#define PB_CA   (NROWS_*DIM_/4/384)          // 4096
#define PB_CT   ((DIM_/32)*(DIM_/32)*2)      // 1152
#define PB_CW   ((NCAT*DIM_)/384)            // 192
#define PB_TOT  (PB_LN + PB_CA + PB_CT + PB_CW)

__global__ __launch_bounds__(384) void prologue_kernel(
    const float* __restrict__ query,
    const float* __restrict__ lnw, const float* __restrict__ lnb,
    const float* __restrict__ feat,
    const float* __restrict__ vpw, const float* __restrict__ outw,
    const float* __restrict__ offw, const float* __restrict__ offb,
    const float* __restrict__ aww,  const float* __restrict__ awb)
{
    __shared__ __align__(16) float sh[32 * 33];   // convT tile / ln reductions
    int bid = blockIdx.x;
    int tid = threadIdx.x;

    if (bid < PB_LN) {
        // ---- layernorm row ----
        int row = bid;
        const float2* x = (const float2*)(query + (size_t)row * DIM_);
        float2 v = x[tid];
        float s = v.x + v.y;
        float* red  = sh;
        float* red2 = sh + 16;
        #pragma unroll
        for (int o = 16; o; o >>= 1) s += __shfl_xor_sync(0xffffffffu, s, o);
        if ((tid & 31) == 0) red[tid >> 5] = s;
        __syncthreads();
        if (tid < 32) {
            float t = (tid < 12) ? red[tid] : 0.f;
            #pragma unroll
            for (int o = 8; o; o >>= 1) t += __shfl_xor_sync(0xffffffffu, t, o);
            if (tid == 0) red[0] = t;
        }
        __syncthreads();
        float mean = red[0] * (1.f / DIM_);
        float d0 = v.x - mean, d1 = v.y - mean;
        s = d0 * d0 + d1 * d1;
        #pragma unroll
        for (int o = 16; o; o >>= 1) s += __shfl_xor_sync(0xffffffffu, s, o);
        if ((tid & 31) == 0) red2[tid >> 5] = s;
        __syncthreads();
        if (tid < 32) {
            float t = (tid < 12) ? red2[tid] : 0.f;
            #pragma unroll
            for (int o = 8; o; o >>= 1) t += __shfl_xor_sync(0xffffffffu, t, o);
            if (tid == 0) red2[0] = t;
        }
        __syncthreads();
        float rstd = rsqrtf(red2[0] * (1.f / DIM_) + 1e-6f);
        float2 ww = ((const float2*)lnw)[tid];
        float2 bb = ((const float2*)lnb)[tid];
        float o0 = d0 * rstd * ww.x + bb.x;
        float o1 = d1 * rstd * ww.y + bb.y;
        uint32_t pk;
        asm("cvt.rn.bf16x2.f32 %0, %1, %2;" : "=r"(pk) : "f"(o1), "f"(o0));
        ((uint32_t*)(g_qnb + (size_t)row * DIM_))[tid] = pk;
    } else if (bid < PB_LN + PB_CA) {
        // ---- feat -> bf16 ----
        int i = (bid - PB_LN) * 384 + tid;
        float4 v = ((const float4*)feat)[i];
        uint32_t lo, hi;
        asm("cvt.rn.bf16x2.f32 %0, %1, %2;" : "=r"(lo) : "f"(v.y), "f"(v.x));
        asm("cvt.rn.bf16x2.f32 %0, %1, %2;" : "=r"(hi) : "f"(v.w), "f"(v.z));
        ((uint2*)g_featb)[i] = make_uint2(lo, hi);
    } else if (bid < PB_LN + PB_CA + PB_CT) {
        // ---- weight transpose 32x32 tile ----
        int t = bid - (PB_LN + PB_CA);
        int z = t / 576;
        int rem = t % 576;
        const float* W    = z ? outw : vpw;
        __nv_bfloat16* Wt = z ? g_outwt : g_vpwt;
        int bx = (rem % 24) * 32, by = (rem / 24) * 32;
        int tx = tid & 31, ty = (tid >> 5);   // 12 rows of 32, use first 8
        if (ty < 8) {
            #pragma unroll
            for (int i = 0; i < 32; i += 8)
                sh[(ty + i) * 33 + tx] = W[(size_t)(by + ty + i) * DIM_ + bx + tx];
        }
        __syncthreads();
        if (ty < 8) {
            #pragma unroll
            for (int i = 0; i < 32; i += 8)
                Wt[(size_t)(bx + ty + i) * DIM_ + by + tx] =
                    __float2bfloat16(sh[tx * 33 + ty + i]);
        }
    } else {
        // ---- concat off/aw weights ----
        int lb = bid - (PB_LN + PB_CA + PB_CT);
        int i = lb * 384 + tid;
        int c = i / DIM_, k = i % DIM_;
        float v = 0.f;
        if (c < 48)      v = offw[(size_t)k * 48 + c];
        else if (c < 72) v = aww[(size_t)k * 24 + (c - 48)];
        g_catwt[i] = __float2bfloat16(v);
        if (lb == 0 && tid < NCAT)
            g_bcat[tid] = (tid < 48) ? offb[tid] : (tid < 72 ? awb[tid - 48] : 0.f);
    }
}

// ---------------- HMMA bf16 GEMM: tile 128x96 ----------------
#define KC       32
#define RSB      80
#define A_BYTES  (128 * RSB)
#define B_BYTES  (96 * RSB)
#define STAGE_B  (A_BYTES + B_BYTES)
#define NSTEP    (DIM_ / KC)

template <int MODE>
__global__ __launch_bounds__(256, 2) void gemm_bf16(
    const __nv_bfloat16* __restrict__ A, const __nv_bfloat16* __restrict__ Bt,
    const float* __restrict__ bias, void* __restrict__ Cout, int ldc,
    const float* __restrict__ resid, const float* __restrict__ gamma)
{
    extern __shared__ __align__(128) char dsm[];
    uint32_t sb = smem_u32(dsm);
    int tid = threadIdx.x, wid = tid >> 5, lane = tid & 31;
    int n0 = blockIdx.x * 96, m0 = blockIdx.y * 128;
    int wm = (wid & 3) * 32;
    int wn = (wid >> 2) * 48;

    int arow[2], alc[2];
    #pragma unroll
    for (int j = 0; j < 2; j++) {
        int id = j * 256 + tid;
        arow[j] = id >> 2;
        alc[j]  = (id & 3) * 8;
    }
    int brow0 = tid >> 2,          blc0 = (tid & 3) * 8;
    int brow1 = (256 + tid) >> 2,  blc1 = (tid & 3) * 8;
    bool bj1 = tid < 128;

    auto load_stage = [&](int s) {
        uint32_t base = sb + (s & 3) * STAGE_B;
        int k0 = s * KC;
        #pragma unroll
        for (int j = 0; j < 2; j++)
            cp16(base + arow[j] * RSB + alc[j] * 2,
                 A + (size_t)(m0 + arow[j]) * DIM_ + k0 + alc[j]);
        cp16(base + A_BYTES + brow0 * RSB + blc0 * 2,
             Bt + (size_t)(n0 + brow0) * DIM_ + k0 + blc0);
        if (bj1)
            cp16(base + A_BYTES + brow1 * RSB + blc1 * 2,
                 Bt + (size_t)(n0 + brow1) * DIM_ + k0 + blc1);
        CP_COMMIT();
    };

    float acc[2][6][4] = {};

    load_stage(0); load_stage(1); load_stage(2);

    for (int s = 0; s < NSTEP; s++) {
        if (s + 3 < NSTEP) {
            asm volatile("cp.async.wait_group 2;" ::: "memory");
            __syncthreads();
            load_stage(s + 3);
        } else if (s + 3 == NSTEP) {
            asm volatile("cp.async.wait_group 2;" ::: "memory");
            __syncthreads();
        } else if (s + 2 == NSTEP) {
            asm volatile("cp.async.wait_group 1;" ::: "memory");
            __syncthreads();
        } else {
            asm volatile("cp.async.wait_group 0;" ::: "memory");
            __syncthreads();
        }

        uint32_t abase = sb + (s & 3) * STAGE_B;
        uint32_t bbase = abase + A_BYTES;
        #pragma unroll
        for (int kk = 0; kk < 2; kk++) {
            uint32_t af[2][4], bf[3][4];
            #pragma unroll
            for (int mt = 0; mt < 2; mt++) {
                int r  = wm + mt * 16 + (lane & 15);
                int kc = kk * 16 + (lane >> 4) * 8;
                ldsm4(af[mt][0], af[mt][1], af[mt][2], af[mt][3],
                      abase + r * RSB + kc * 2);
            }
            #pragma unroll
            for (int np = 0; np < 3; np++) {
                int n  = wn + np * 16 + (lane & 7) + ((lane >> 4) << 3);
                int kc = kk * 16 + ((lane >> 3) & 1) * 8;
                ldsm4(bf[np][0], bf[np][1], bf[np][2], bf[np][3],
                      bbase + n * RSB + kc * 2);
            }
            #pragma unroll
            for (int mt = 0; mt < 2; mt++)
                #pragma unroll
                for (int nt = 0; nt < 6; nt++)
                    mma_bf16(acc[mt][nt], af[mt], &bf[nt >> 1][(nt & 1) * 2]);
        }
    }

    int crow0 = m0 + wm + (lane >> 2);
    int ccol0 = n0 + wn + (lane & 3) * 2;
    #pragma unroll
    for (int mt = 0; mt < 2; mt++) {
        #pragma unroll
        for (int half = 0; half < 2; half++) {
            int row = crow0 + mt * 16 + half * 8;
            #pragma unroll
            for (int nt = 0; nt < 6; nt++) {
                int col = ccol0 + nt * 8;
                float f0 = acc[mt][nt][half * 2]     + bias[col];
                float f1 = acc[mt][nt][half * 2 + 1] + bias[col + 1];
                if (MODE == 0) {
                    uint32_t pk;
                    asm("cvt.rn.bf16x2.f32 %0, %1, %2;" : "=r"(pk) : "f"(f1), "f"(f0));
                    *(uint32_t*)((__nv_bfloat16*)Cout + (size_t)row * ldc + col) = pk;
                } else if (MODE == 1) {
                    const float* qr = resid + (size_t)row * ldc + col;
                    float2 o;
                    o.x = qr[0] + gamma[col]     * f0;
                    o.y = qr[1] + gamma[col + 1] * f1;
                    *(float2*)((float*)Cout + (size_t)row * ldc + col) = o;
                } else {
                    float2 o; o.x = f0; o.y = f1;
                    *(float2*)((float*)Cout + (size_t)row * ldc + col) = o;
                }
            }
        }
    }
}

// ---------------- bilinear sampling with inline softmax/locations ----------------
__global__ __launch_bounds__(256) void sample_kernel(const float* __restrict__ refp)
{
    int w = blockIdx.x * 8 + (threadIdx.x >> 5);
    int lane = threadIdx.x & 31;
    int h  = w % HEADS_;
    int qi = w / HEADS_;
    int b  = qi >> 12;

    const float* lg = g_logits + (size_t)qi * NCAT;
    // softmax over logits[48..71] (24 attention weights)
    float x = (lane < 24) ? lg[48 + lane] : -1e30f;
    float m = x;
    #pragma unroll
    for (int o = 16; o; o >>= 1) m = fmaxf(m, __shfl_xor_sync(0xffffffffu, m, o));
    float e = (lane < 24) ? __expf(x - m) : 0.f;
    float ss = e;
    #pragma unroll
    for (int o = 16; o; o >>= 1) ss += __shfl_xor_sync(0xffffffffu, ss, o);
    float p_all = e / ss;                                  // lane j: aw for flat index j
    float off = (lane < 8) ? lg[h * 8 + lane] : 0.f;       // this head's 8 offsets
    float rx = refp[(size_t)qi * 2 + 0];
    float ry = refp[(size_t)qi * 2 + 1];

    float a0 = 0.f, a1 = 0.f, a2 = 0.f, a3 = 0.f;
    const __nv_bfloat162* val2 =
        (const __nv_bfloat162*)(g_valb + (size_t)b * NQ_ * DIM_ + h * HD_);
    #pragma unroll
    for (int p = 0; p < POINTS_; p++) {
        float aw = __shfl_sync(0xffffffffu, p_all, h * POINTS_ + p);
        float ox = __shfl_sync(0xffffffffu, off, p * 2);
        float oy = __shfl_sync(0xffffffffu, off, p * 2 + 1);
        float lx = rx + ox * (1.f / 64.f);
        float ly = ry + oy * (1.f / 64.f);
        float xf = lx * HW_ - 0.5f;
        float yf = ly * HW_ - 0.5f;
        float x0f = floorf(xf), y0f = floorf(yf);
        float wx = xf - x0f, wy = yf - y0f;
        int x0 = (int)x0f, y0 = (int)y0f;
        #pragma unroll
        for (int dy = 0; dy < 2; dy++) {
            #pragma unroll
            for (int dx = 0; dx < 2; dx++) {
                int xi = x0 + dx, yi = y0 + dy;
                if (xi < 0 || xi >= HW_ || yi < 0 || yi >= HW_) continue;
                float cw = aw * (dy ? wy : 1.f - wy) * (dx ? wx : 1.f - wx);
                const __nv_bfloat162* vv = val2 + (size_t)(yi * HW_ + xi) * (DIM_ / 2);
                float2 f0 = __bfloat1622float2(vv[lane]);
                float2 f1 = __bfloat1622float2(vv[lane + 32]);
                a0 = fmaf(cw, f0.x, a0);
                a1 = fmaf(cw, f0.y, a1);
                a2 = fmaf(cw, f1.x, a2);
                a3 = fmaf(cw, f1.y, a3);
            }
        }
    }
    __nv_bfloat162* o2 = (__nv_bfloat162*)(g_attnb + (size_t)qi * DIM_ + h * HD_);
    o2[lane]      = __floats2bfloat162_rn(a0, a1);
    o2[lane + 32] = __floats2bfloat162_rn(a2, a3);
}

// ---------------- launch ----------------
extern "C" void kernel_launch(void* const* d_in, const int* in_sizes, int n_in,
                              void* d_out, int out_size)
{
    const float* query = (const float*)d_in[0];
    const float* refp  = (const float*)d_in[1];
    const float* feat  = (const float*)d_in[2];
    const float* lnw   = (const float*)d_in[5];
    const float* lnb   = (const float*)d_in[6];
    const float* vpw   = (const float*)d_in[7];
    const float* vpb   = (const float*)d_in[8];
    const float* offw  = (const float*)d_in[9];
    const float* offb  = (const float*)d_in[10];
    const float* aww   = (const float*)d_in[11];
    const float* awb   = (const float*)d_in[12];
    const float* outw  = (const float*)d_in[13];
    const float* outb  = (const float*)d_in[14];
    const float* gamma = (const float*)d_in[15];
    float* out = (float*)d_out;

    __nv_bfloat16 *p_featb, *p_valb, *p_attnb, *p_vpwt, *p_outwt, *p_catwt, *p_qnb;
    float *p_bcat, *p_logits;
    cudaGetSymbolAddress((void**)&p_featb, g_featb);
    cudaGetSymbolAddress((void**)&p_valb,  g_valb);
    cudaGetSymbolAddress((void**)&p_attnb, g_attnb);
    cudaGetSymbolAddress((void**)&p_vpwt,  g_vpwt);
    cudaGetSymbolAddress((void**)&p_outwt, g_outwt);
    cudaGetSymbolAddress((void**)&p_catwt, g_catwt);
    cudaGetSymbolAddress((void**)&p_qnb,   g_qnb);
    cudaGetSymbolAddress((void**)&p_bcat,  g_bcat);
    cudaGetSymbolAddress((void**)&p_logits,g_logits);

    const int SMEM = 4 * STAGE_B;
    cudaFuncSetAttribute(gemm_bf16<0>, cudaFuncAttributeMaxDynamicSharedMemorySize, SMEM);
    cudaFuncSetAttribute(gemm_bf16<1>, cudaFuncAttributeMaxDynamicSharedMemorySize, SMEM);
    cudaFuncSetAttribute(gemm_bf16<2>, cudaFuncAttributeMaxDynamicSharedMemorySize, SMEM);

    dim3 gg(DIM_ / 96, NROWS_ / 128);       // (8, 64)
    dim3 gl(1, NROWS_ / 128);               // (1, 64)

    prologue_kernel<<<PB_TOT, 384>>>(query, lnw, lnb, feat, vpw, outw,
                                     offw, offb, aww, awb);
    gemm_bf16<0><<<gg, 256, SMEM>>>(p_featb, p_vpwt, vpb, p_valb, DIM_, nullptr, nullptr);
    gemm_bf16<2><<<gl, 256, SMEM>>>(p_qnb, p_catwt, p_bcat, p_logits, NCAT, nullptr, nullptr);
    sample_kernel<<<NROWS_ * HEADS_ / 8, 256>>>(refp);
    gemm_bf16<1><<<gg, 256, SMEM>>>(p_attnb, p_outwt, outb, out, DIM_, query, gamma);
}

// round 9
// speedup vs baseline: 5.8209x; 1.1022x over previous
#include <cuda_runtime.h>
#include <cuda_bf16.h>
#include <math.h>
#include <cstdint>

#define BS_    2
#define NQ_    4096
#define DIM_   768
#define HEADS_ 6
#define POINTS_ 4
#define HD_    128
#define HW_    64
#define NROWS_ (BS_*NQ_)   // 8192
#define NCAT   96

// ---------------- scratch ----------------
__device__ __align__(128) __nv_bfloat16 g_qnb  [NROWS_*DIM_];
__device__ __align__(128) __nv_bfloat16 g_featb[NROWS_*DIM_];
__device__ __align__(128) __nv_bfloat16 g_valb [NROWS_*DIM_];
__device__ __align__(128) __nv_bfloat16 g_attnb[NROWS_*DIM_];
__device__ __align__(128) __nv_bfloat16 g_vpwt [DIM_*DIM_];
__device__ __align__(128) __nv_bfloat16 g_outwt[DIM_*DIM_];
__device__ __align__(128) __nv_bfloat16 g_catwt[NCAT*DIM_];
__device__ __align__(128) float g_bcat[NCAT];
__device__ __align__(128) float g_logits[NROWS_*NCAT];

// ================= PTX helpers =================
__device__ __forceinline__ uint32_t smem_u32(const void* p) {
    uint32_t a;
    asm("{ .reg .u64 t; cvta.to.shared.u64 t, %1; cvt.u32.u64 %0, t; }" : "=r"(a) : "l"(p));
    return a;
}
__device__ __forceinline__ void cp16(uint32_t dst, const void* src) {
    asm volatile("cp.async.cg.shared.global [%0], [%1], 16;" :: "r"(dst), "l"(src));
}
#define CP_COMMIT() asm volatile("cp.async.commit_group;" ::: "memory")

__device__ __forceinline__ void ldsm4(uint32_t& r0, uint32_t& r1, uint32_t& r2, uint32_t& r3,
                                      uint32_t addr) {
    asm volatile("ldmatrix.sync.aligned.m8n8.x4.shared.b16 {%0,%1,%2,%3}, [%4];"
                 : "=r"(r0), "=r"(r1), "=r"(r2), "=r"(r3) : "r"(addr));
}
__device__ __forceinline__ void mma_bf16(float* c, const uint32_t* a, const uint32_t* b) {
    asm volatile("mma.sync.aligned.m16n8k16.row.col.f32.bf16.bf16.f32 "
                 "{%0,%1,%2,%3}, {%4,%5,%6,%7}, {%8,%9}, {%0,%1,%2,%3};"
                 : "+f"(c[0]), "+f"(c[1]), "+f"(c[2]), "+f"(c[3])
                 : "r"(a[0]), "r"(a[1]), "r"(a[2]), "r"(a[3]), "r"(b[0]), "r"(b[1]));
}

// ---------------- fused prologue: ln | convA | convT x2 | convW ----------------
#define PB_LN   NROWS_
#define PB_CA   (NROWS_*DIM_/4/384)          // 4096
#define PB_CT   ((DIM_/32)*(DIM_/32)*2)      // 1152
#define PB_CW   ((NCAT*DIM_)/384)            // 192
#define PB_TOT  (PB_LN + PB_CA + PB_CT + PB_CW)

__global__ __launch_bounds__(384) void prologue_kernel(
    const float* __restrict__ query,
    const float* __restrict__ lnw, const float* __restrict__ lnb,
    const float* __restrict__ feat,
    const float* __restrict__ vpw, const float* __restrict__ outw,
    const float* __restrict__ offw, const float* __restrict__ offb,
    const float* __restrict__ aww,  const float* __restrict__ awb)
{
    __shared__ __align__(16) float sh[32 * 33];
    int bid = blockIdx.x;
    int tid = threadIdx.x;

    if (bid < PB_LN) {
        int row = bid;
        const float2* x = (const float2*)(query + (size_t)row * DIM_);
        float2 v = x[tid];
        float s = v.x + v.y;
        float* red  = sh;
        float* red2 = sh + 16;
        #pragma unroll
        for (int o = 16; o; o >>= 1) s += __shfl_xor_sync(0xffffffffu, s, o);
        if ((tid & 31) == 0) red[tid >> 5] = s;
        __syncthreads();
        if (tid < 32) {
            float t = (tid < 12) ? red[tid] : 0.f;
            #pragma unroll
            for (int o = 8; o; o >>= 1) t += __shfl_xor_sync(0xffffffffu, t, o);
            if (tid == 0) red[0] = t;
        }
        __syncthreads();
        float mean = red[0] * (1.f / DIM_);
        float d0 = v.x - mean, d1 = v.y - mean;
        s = d0 * d0 + d1 * d1;
        #pragma unroll
        for (int o = 16; o; o >>= 1) s += __shfl_xor_sync(0xffffffffu, s, o);
        if ((tid & 31) == 0) red2[tid >> 5] = s;
        __syncthreads();
        if (tid < 32) {
            float t = (tid < 12) ? red2[tid] : 0.f;
            #pragma unroll
            for (int o = 8; o; o >>= 1) t += __shfl_xor_sync(0xffffffffu, t, o);
            if (tid == 0) red2[0] = t;
        }
        __syncthreads();
        float rstd = rsqrtf(red2[0] * (1.f / DIM_) + 1e-6f);
        float2 ww = ((const float2*)lnw)[tid];
        float2 bb = ((const float2*)lnb)[tid];
        float o0 = d0 * rstd * ww.x + bb.x;
        float o1 = d1 * rstd * ww.y + bb.y;
        uint32_t pk;
        asm("cvt.rn.bf16x2.f32 %0, %1, %2;" : "=r"(pk) : "f"(o1), "f"(o0));
        ((uint32_t*)(g_qnb + (size_t)row * DIM_))[tid] = pk;
    } else if (bid < PB_LN + PB_CA) {
        int i = (bid - PB_LN) * 384 + tid;
        float4 v = ((const float4*)feat)[i];
        uint32_t lo, hi;
        asm("cvt.rn.bf16x2.f32 %0, %1, %2;" : "=r"(lo) : "f"(v.y), "f"(v.x));
        asm("cvt.rn.bf16x2.f32 %0, %1, %2;" : "=r"(hi) : "f"(v.w), "f"(v.z));
        ((uint2*)g_featb)[i] = make_uint2(lo, hi);
    } else if (bid < PB_LN + PB_CA + PB_CT) {
        int t = bid - (PB_LN + PB_CA);
        int z = t / 576;
        int rem = t % 576;
        const float* W    = z ? outw : vpw;
        __nv_bfloat16* Wt = z ? g_outwt : g_vpwt;
        int bx = (rem % 24) * 32, by = (rem / 24) * 32;
        int tx = tid & 31, ty = (tid >> 5);
        if (ty < 8) {
            #pragma unroll
            for (int i = 0; i < 32; i += 8)
                sh[(ty + i) * 33 + tx] = W[(size_t)(by + ty + i) * DIM_ + bx + tx];
        }
        __syncthreads();
        if (ty < 8) {
            #pragma unroll
            for (int i = 0; i < 32; i += 8)
                Wt[(size_t)(bx + ty + i) * DIM_ + by + tx] =
                    __float2bfloat16(sh[tx * 33 + ty + i]);
        }
    } else {
        int lb = bid - (PB_LN + PB_CA + PB_CT);
        int i = lb * 384 + tid;
        int c = i / DIM_, k = i % DIM_;
        float v = 0.f;
        if (c < 48)      v = offw[(size_t)k * 48 + c];
        else if (c < 72) v = aww[(size_t)k * 24 + (c - 48)];
        g_catwt[i] = __float2bfloat16(v);
        if (lb == 0 && tid < NCAT)
            g_bcat[tid] = (tid < 48) ? offb[tid] : (tid < 72 ? awb[tid - 48] : 0.f);
    }
}

// ---------------- HMMA bf16 GEMM: tile 128x96 ----------------
// MODE 0: main value GEMM (bf16 out) + fused logits tile at blockIdx.x==8 (fp32 out)
// MODE 1: C = fp32(resid + gamma*(acc + bias))
#define KC       32
#define RSB      80
#define A_BYTES  (128 * RSB)
#define B_BYTES  (96 * RSB)
#define STAGE_B  (A_BYTES + B_BYTES)
#define NSTEP    (DIM_ / KC)

template <int MODE>
__global__ __launch_bounds__(256, 2) void gemm_bf16(
    const __nv_bfloat16* __restrict__ A, const __nv_bfloat16* __restrict__ Bt,
    const float* __restrict__ bias, void* __restrict__ Cout, int ldc,
    const float* __restrict__ resid, const float* __restrict__ gamma)
{
    extern __shared__ __align__(128) char dsm[];
    uint32_t sb = smem_u32(dsm);
    int tid = threadIdx.x, wid = tid >> 5, lane = tid & 31;
    int m0 = blockIdx.y * 128;
    int wm = (wid & 3) * 32;
    int wn = (wid >> 2) * 48;

    bool lgt = (MODE == 0) && (blockIdx.x == 8);
    const __nv_bfloat16* Ap  = lgt ? g_qnb   : A;
    const __nv_bfloat16* Bp  = lgt ? g_catwt : Bt;
    const float*         bp  = lgt ? g_bcat  : bias;
    int n0  = lgt ? 0 : blockIdx.x * 96;
    int ldcc = lgt ? NCAT : ldc;

    int arow[2], alc[2];
    #pragma unroll
    for (int j = 0; j < 2; j++) {
        int id = j * 256 + tid;
        arow[j] = id >> 2;
        alc[j]  = (id & 3) * 8;
    }
    int brow0 = tid >> 2,          blc0 = (tid & 3) * 8;
    int brow1 = (256 + tid) >> 2,  blc1 = (tid & 3) * 8;
    bool bj1 = tid < 128;

    auto load_stage = [&](int s) {
        uint32_t base = sb + (s & 3) * STAGE_B;
        int k0 = s * KC;
        #pragma unroll
        for (int j = 0; j < 2; j++)
            cp16(base + arow[j] * RSB + alc[j] * 2,
                 Ap + (size_t)(m0 + arow[j]) * DIM_ + k0 + alc[j]);
        cp16(base + A_BYTES + brow0 * RSB + blc0 * 2,
             Bp + (size_t)(n0 + brow0) * DIM_ + k0 + blc0);
        if (bj1)
            cp16(base + A_BYTES + brow1 * RSB + blc1 * 2,
                 Bp + (size_t)(n0 + brow1) * DIM_ + k0 + blc1);
        CP_COMMIT();
    };

    float acc[2][6][4] = {};

    load_stage(0); load_stage(1); load_stage(2);

    for (int s = 0; s < NSTEP; s++) {
        if (s + 3 < NSTEP) {
            asm volatile("cp.async.wait_group 2;" ::: "memory");
            __syncthreads();
            load_stage(s + 3);
        } else if (s + 3 == NSTEP) {
            asm volatile("cp.async.wait_group 2;" ::: "memory");
            __syncthreads();
        } else if (s + 2 == NSTEP) {
            asm volatile("cp.async.wait_group 1;" ::: "memory");
            __syncthreads();
        } else {
            asm volatile("cp.async.wait_group 0;" ::: "memory");
            __syncthreads();
        }

        uint32_t abase = sb + (s & 3) * STAGE_B;
        uint32_t bbase = abase + A_BYTES;
        #pragma unroll
        for (int kk = 0; kk < 2; kk++) {
            uint32_t af[2][4], bf[3][4];
            #pragma unroll
            for (int mt = 0; mt < 2; mt++) {
                int r  = wm + mt * 16 + (lane & 15);
                int kc = kk * 16 + (lane >> 4) * 8;
                ldsm4(af[mt][0], af[mt][1], af[mt][2], af[mt][3],
                      abase + r * RSB + kc * 2);
            }
            #pragma unroll
            for (int np = 0; np < 3; np++) {
                int n  = wn + np * 16 + (lane & 7) + ((lane >> 4) << 3);
                int kc = kk * 16 + ((lane >> 3) & 1) * 8;
                ldsm4(bf[np][0], bf[np][1], bf[np][2], bf[np][3],
                      bbase + n * RSB + kc * 2);
            }
            #pragma unroll
            for (int mt = 0; mt < 2; mt++)
                #pragma unroll
                for (int nt = 0; nt < 6; nt++)
                    mma_bf16(acc[mt][nt], af[mt], &bf[nt >> 1][(nt & 1) * 2]);
        }
    }

    int crow0 = m0 + wm + (lane >> 2);
    int ccol0 = n0 + wn + (lane & 3) * 2;
    #pragma unroll
    for (int mt = 0; mt < 2; mt++) {
        #pragma unroll
        for (int half = 0; half < 2; half++) {
            int row = crow0 + mt * 16 + half * 8;
            #pragma unroll
            for (int nt = 0; nt < 6; nt++) {
                int col = ccol0 + nt * 8;
                float f0 = acc[mt][nt][half * 2]     + bp[col];
                float f1 = acc[mt][nt][half * 2 + 1] + bp[col + 1];
                if (MODE == 0) {
                    if (lgt) {
                        float2 o; o.x = f0; o.y = f1;
                        *(float2*)(g_logits + (size_t)row * NCAT + col) = o;
                    } else {
                        uint32_t pk;
                        asm("cvt.rn.bf16x2.f32 %0, %1, %2;" : "=r"(pk) : "f"(f1), "f"(f0));
                        *(uint32_t*)((__nv_bfloat16*)Cout + (size_t)row * ldcc + col) = pk;
                    }
                } else {
                    const float* qr = resid + (size_t)row * ldcc + col;
                    float2 o;
                    o.x = qr[0] + gamma[col]     * f0;
                    o.y = qr[1] + gamma[col + 1] * f1;
                    *(float2*)((float*)Cout + (size_t)row * ldcc + col) = o;
                }
            }
        }
    }
}

// ---------------- bilinear sampling: branchless, 1 uint2 load per corner ----------
__global__ __launch_bounds__(256) void sample_kernel(const float* __restrict__ refp)
{
    int w = blockIdx.x * 8 + (threadIdx.x >> 5);
    int lane = threadIdx.x & 31;
    int h  = w % HEADS_;
    int qi = w / HEADS_;
    int b  = qi >> 12;

    const float* lg = g_logits + (size_t)qi * NCAT;
    float x = (lane < 24) ? lg[48 + lane] : -1e30f;
    float m = x;
    #pragma unroll
    for (int o = 16; o; o >>= 1) m = fmaxf(m, __shfl_xor_sync(0xffffffffu, m, o));
    float e = (lane < 24) ? __expf(x - m) : 0.f;
    float ss = e;
    #pragma unroll
    for (int o = 16; o; o >>= 1) ss += __shfl_xor_sync(0xffffffffu, ss, o);
    float p_all = e / ss;
    float off = (lane < 8) ? lg[h * 8 + lane] : 0.f;
    float rx = refp[(size_t)qi * 2 + 0] * (float)HW_ - 0.5f;
    float ry = refp[(size_t)qi * 2 + 1] * (float)HW_ - 0.5f;

    float a0 = 0.f, a1 = 0.f, a2 = 0.f, a3 = 0.f;
    // lane owns elements [lane*4, lane*4+4) of the 128-wide head slice
    const uint2* vp = (const uint2*)(g_valb + (size_t)b * NQ_ * DIM_ + h * HD_) + lane;
    const int POS = DIM_ / 4;   // uint2 stride per spatial position = 192

    #pragma unroll
    for (int p = 0; p < POINTS_; p++) {
        float aw = __shfl_sync(0xffffffffu, p_all, h * POINTS_ + p);
        float xf = rx + __shfl_sync(0xffffffffu, off, p * 2);
        float yf = ry + __shfl_sync(0xffffffffu, off, p * 2 + 1);
        float x0f = floorf(xf), y0f = floorf(yf);
        float wx = xf - x0f, wy = yf - y0f;
        int x0 = (int)x0f, y0 = (int)y0f;
        #pragma unroll
        for (int dy = 0; dy < 2; dy++) {
            #pragma unroll
            for (int dx = 0; dx < 2; dx++) {
                int xi = x0 + dx, yi = y0 + dy;
                bool v = (xi >= 0) & (xi < HW_) & (yi >= 0) & (yi < HW_);
                int xc = min(max(xi, 0), HW_ - 1);
                int yc = min(max(yi, 0), HW_ - 1);
                float cw = aw * (dy ? wy : 1.f - wy) * (dx ? wx : 1.f - wx);
                cw = v ? cw : 0.f;
                uint2 q = vp[(yc * HW_ + xc) * POS];
                float2 f0 = __bfloat1622float2(*(__nv_bfloat162*)&q.x);
                float2 f1 = __bfloat1622float2(*(__nv_bfloat162*)&q.y);
                a0 = fmaf(cw, f0.x, a0);
                a1 = fmaf(cw, f0.y, a1);
                a2 = fmaf(cw, f1.x, a2);
                a3 = fmaf(cw, f1.y, a3);
            }
        }
    }
    uint2 pk;
    asm("cvt.rn.bf16x2.f32 %0, %1, %2;" : "=r"(pk.x) : "f"(a1), "f"(a0));
    asm("cvt.rn.bf16x2.f32 %0, %1, %2;" : "=r"(pk.y) : "f"(a3), "f"(a2));
    ((uint2*)(g_attnb + (size_t)qi * DIM_ + h * HD_))[lane] = pk;
}

// ---------------- launch ----------------
extern "C" void kernel_launch(void* const* d_in, const int* in_sizes, int n_in,
                              void* d_out, int out_size)
{
    const float* query = (const float*)d_in[0];
    const float* refp  = (const float*)d_in[1];
    const float* feat  = (const float*)d_in[2];
    const float* lnw   = (const float*)d_in[5];
    const float* lnb   = (const float*)d_in[6];
    const float* vpw   = (const float*)d_in[7];
    const float* vpb   = (const float*)d_in[8];
    const float* offw  = (const float*)d_in[9];
    const float* offb  = (const float*)d_in[10];
    const float* aww   = (const float*)d_in[11];
    const float* awb   = (const float*)d_in[12];
    const float* outw  = (const float*)d_in[13];
    const float* outb  = (const float*)d_in[14];
    const float* gamma = (const float*)d_in[15];
    float* out = (float*)d_out;

    __nv_bfloat16 *p_featb, *p_valb, *p_attnb, *p_vpwt, *p_outwt;
    cudaGetSymbolAddress((void**)&p_featb, g_featb);
    cudaGetSymbolAddress((void**)&p_valb,  g_valb);
    cudaGetSymbolAddress((void**)&p_attnb, g_attnb);
    cudaGetSymbolAddress((void**)&p_vpwt,  g_vpwt);
    cudaGetSymbolAddress((void**)&p_outwt, g_outwt);

    const int SMEM = 4 * STAGE_B;
    cudaFuncSetAttribute(gemm_bf16<0>, cudaFuncAttributeMaxDynamicSharedMemorySize, SMEM);
    cudaFuncSetAttribute(gemm_bf16<1>, cudaFuncAttributeMaxDynamicSharedMemorySize, SMEM);

    dim3 g0(DIM_ / 96 + 1, NROWS_ / 128);   // (9, 64): 8 value tiles + 1 logits tile
    dim3 g1(DIM_ / 96, NROWS_ / 128);       // (8, 64)

    prologue_kernel<<<PB_TOT, 384>>>(query, lnw, lnb, feat, vpw, outw,
                                     offw, offb, aww, awb);
    gemm_bf16<0><<<g0, 256, SMEM>>>(p_featb, p_vpwt, vpb, p_valb, DIM_, nullptr, nullptr);
    sample_kernel<<<NROWS_ * HEADS_ / 8, 256>>>(refp);
    gemm_bf16<1><<<g1, 256, SMEM>>>(p_attnb, p_outwt, outb, out, DIM_, query, gamma);
}

// round 10
// speedup vs baseline: 6.0233x; 1.0348x over previous
#include <cuda_runtime.h>
#include <cuda_bf16.h>
#include <math.h>
#include <cstdint>

#define BS_    2
#define NQ_    4096
#define DIM_   768
#define HEADS_ 6
#define POINTS_ 4
#define HD_    128
#define HW_    64
#define NROWS_ (BS_*NQ_)   // 8192
#define NCAT   96

// ---------------- scratch ----------------
__device__ __align__(128) __nv_bfloat16 g_qnb  [NROWS_*DIM_];
__device__ __align__(128) __nv_bfloat16 g_featb[NROWS_*DIM_];
__device__ __align__(128) __nv_bfloat16 g_valb [NROWS_*DIM_];
__device__ __align__(128) __nv_bfloat16 g_attnb[NROWS_*DIM_];
__device__ __align__(128) __nv_bfloat16 g_vpwt [DIM_*DIM_];
__device__ __align__(128) __nv_bfloat16 g_outwt[DIM_*DIM_];
__device__ __align__(128) __nv_bfloat16 g_catwt[NCAT*DIM_];
__device__ __align__(128) float g_bcat[NCAT];
__device__ __align__(128) float g_logits[NROWS_*NCAT];

// ================= PTX helpers =================
__device__ __forceinline__ uint32_t smem_u32(const void* p) {
    uint32_t a;
    asm("{ .reg .u64 t; cvta.to.shared.u64 t, %1; cvt.u32.u64 %0, t; }" : "=r"(a) : "l"(p));
    return a;
}
__device__ __forceinline__ void cp16(uint32_t dst, const void* src) {
    asm volatile("cp.async.cg.shared.global [%0], [%1], 16;" :: "r"(dst), "l"(src));
}
#define CP_COMMIT() asm volatile("cp.async.commit_group;" ::: "memory")

__device__ __forceinline__ void ldsm4(uint32_t* r, uint32_t addr) {
    asm volatile("ldmatrix.sync.aligned.m8n8.x4.shared.b16 {%0,%1,%2,%3}, [%4];"
                 : "=r"(r[0]), "=r"(r[1]), "=r"(r[2]), "=r"(r[3]) : "r"(addr));
}
__device__ __forceinline__ void mma_bf16(float* c, const uint32_t* a, const uint32_t* b) {
    asm volatile("mma.sync.aligned.m16n8k16.row.col.f32.bf16.bf16.f32 "
                 "{%0,%1,%2,%3}, {%4,%5,%6,%7}, {%8,%9}, {%0,%1,%2,%3};"
                 : "+f"(c[0]), "+f"(c[1]), "+f"(c[2]), "+f"(c[3])
                 : "r"(a[0]), "r"(a[1]), "r"(a[2]), "r"(a[3]), "r"(b[0]), "r"(b[1]));
}

// ---------------- fused prologue: ln | convA | convT x2 | convW ----------------
#define PB_LN   NROWS_
#define PB_CA   (NROWS_*DIM_/4/384)          // 4096
#define PB_CT   ((DIM_/32)*(DIM_/32)*2)      // 1152
#define PB_CW   ((NCAT*DIM_)/384)            // 192
#define PB_TOT  (PB_LN + PB_CA + PB_CT + PB_CW)

__global__ __launch_bounds__(384) void prologue_kernel(
    const float* __restrict__ query,
    const float* __restrict__ lnw, const float* __restrict__ lnb,
    const float* __restrict__ feat,
    const float* __restrict__ vpw, const float* __restrict__ outw,
    const float* __restrict__ offw, const float* __restrict__ offb,
    const float* __restrict__ aww,  const float* __restrict__ awb)
{
    __shared__ __align__(16) float sh[32 * 33];
    int bid = blockIdx.x;
    int tid = threadIdx.x;

    if (bid < PB_LN) {
        int row = bid;
        const float2* x = (const float2*)(query + (size_t)row * DIM_);
        float2 v = x[tid];
        float s = v.x + v.y;
        float* red  = sh;
        float* red2 = sh + 16;
        #pragma unroll
        for (int o = 16; o; o >>= 1) s += __shfl_xor_sync(0xffffffffu, s, o);
        if ((tid & 31) == 0) red[tid >> 5] = s;
        __syncthreads();
        if (tid < 32) {
            float t = (tid < 12) ? red[tid] : 0.f;
            #pragma unroll
            for (int o = 8; o; o >>= 1) t += __shfl_xor_sync(0xffffffffu, t, o);
            if (tid == 0) red[0] = t;
        }
        __syncthreads();
        float mean = red[0] * (1.f / DIM_);
        float d0 = v.x - mean, d1 = v.y - mean;
        s = d0 * d0 + d1 * d1;
        #pragma unroll
        for (int o = 16; o; o >>= 1) s += __shfl_xor_sync(0xffffffffu, s, o);
        if ((tid & 31) == 0) red2[tid >> 5] = s;
        __syncthreads();
        if (tid < 32) {
            float t = (tid < 12) ? red2[tid] : 0.f;
            #pragma unroll
            for (int o = 8; o; o >>= 1) t += __shfl_xor_sync(0xffffffffu, t, o);
            if (tid == 0) red2[0] = t;
        }
        __syncthreads();
        float rstd = rsqrtf(red2[0] * (1.f / DIM_) + 1e-6f);
        float2 ww = ((const float2*)lnw)[tid];
        float2 bb = ((const float2*)lnb)[tid];
        float o0 = d0 * rstd * ww.x + bb.x;
        float o1 = d1 * rstd * ww.y + bb.y;
        uint32_t pk;
        asm("cvt.rn.bf16x2.f32 %0, %1, %2;" : "=r"(pk) : "f"(o1), "f"(o0));
        ((uint32_t*)(g_qnb + (size_t)row * DIM_))[tid] = pk;
    } else if (bid < PB_LN + PB_CA) {
        int i = (bid - PB_LN) * 384 + tid;
        float4 v = ((const float4*)feat)[i];
        uint32_t lo, hi;
        asm("cvt.rn.bf16x2.f32 %0, %1, %2;" : "=r"(lo) : "f"(v.y), "f"(v.x));
        asm("cvt.rn.bf16x2.f32 %0, %1, %2;" : "=r"(hi) : "f"(v.w), "f"(v.z));
        ((uint2*)g_featb)[i] = make_uint2(lo, hi);
    } else if (bid < PB_LN + PB_CA + PB_CT) {
        int t = bid - (PB_LN + PB_CA);
        int z = t / 576;
        int rem = t % 576;
        const float* W    = z ? outw : vpw;
        __nv_bfloat16* Wt = z ? g_outwt : g_vpwt;
        int bx = (rem % 24) * 32, by = (rem / 24) * 32;
        int tx = tid & 31, ty = (tid >> 5);
        if (ty < 8) {
            #pragma unroll
            for (int i = 0; i < 32; i += 8)
                sh[(ty + i) * 33 + tx] = W[(size_t)(by + ty + i) * DIM_ + bx + tx];
        }
        __syncthreads();
        if (ty < 8) {
            #pragma unroll
            for (int i = 0; i < 32; i += 8)
                Wt[(size_t)(bx + ty + i) * DIM_ + by + tx] =
                    __float2bfloat16(sh[tx * 33 + ty + i]);
        }
    } else {
        int lb = bid - (PB_LN + PB_CA + PB_CT);
        int i = lb * 384 + tid;
        int c = i / DIM_, k = i % DIM_;
        float v = 0.f;
        if (c < 48)      v = offw[(size_t)k * 48 + c];
        else if (c < 72) v = aww[(size_t)k * 24 + (c - 48)];
        g_catwt[i] = __float2bfloat16(v);
        if (lb == 0 && tid < NCAT)
            g_bcat[tid] = (tid < 48) ? offb[tid] : (tid < 72 ? awb[tid - 48] : 0.f);
    }
}

// ---------------- HMMA bf16 GEMM: CTA tile 128x96, 4 warps of 64x48 ----------------
// MODE 0: value GEMM (bf16 out) + fused logits tile at blockIdx.x==8 (fp32 out)
// MODE 1: C = fp32(resid + gamma*(acc + bias))
#define KC       32
#define RSB      80
#define A_BYTES  (128 * RSB)
#define B_BYTES  (96 * RSB)
#define STAGE_B  (A_BYTES + B_BYTES)
#define NSTEP    (DIM_ / KC)

template <int MODE>
__global__ __launch_bounds__(128, 2) void gemm_bf16(
    const __nv_bfloat16* __restrict__ A, const __nv_bfloat16* __restrict__ Bt,
    const float* __restrict__ bias, void* __restrict__ Cout, int ldc,
    const float* __restrict__ resid, const float* __restrict__ gamma)
{
    extern __shared__ __align__(128) char dsm[];
    uint32_t sb = smem_u32(dsm);
    int tid = threadIdx.x, wid = tid >> 5, lane = tid & 31;
    int m0 = blockIdx.y * 128;
    int wm = (wid & 1) * 64;     // warp tile 64x48, 2x2 warp grid
    int wn = (wid >> 1) * 48;

    bool lgt = (MODE == 0) && (blockIdx.x == 8);
    const __nv_bfloat16* Ap  = lgt ? g_qnb   : A;
    const __nv_bfloat16* Bp  = lgt ? g_catwt : Bt;
    const float*         bp  = lgt ? g_bcat  : bias;
    int n0   = lgt ? 0 : blockIdx.x * 96;
    int ldcc = lgt ? NCAT : ldc;

    // 128 threads: A 512 chunks (4/thread), B 384 chunks (3/thread)
    int ar[4], ac[4];
    #pragma unroll
    for (int j = 0; j < 4; j++) {
        int id = j * 128 + tid;
        ar[j] = id >> 2;
        ac[j] = (id & 3) * 8;
    }
    int br[3], bc[3];
    #pragma unroll
    for (int j = 0; j < 3; j++) {
        int id = j * 128 + tid;
        br[j] = id >> 2;
        bc[j] = (id & 3) * 8;
    }

    auto load_stage = [&](int s) {
        uint32_t base = sb + (s & 3) * STAGE_B;
        int k0 = s * KC;
        #pragma unroll
        for (int j = 0; j < 4; j++)
            cp16(base + ar[j] * RSB + ac[j] * 2,
                 Ap + (size_t)(m0 + ar[j]) * DIM_ + k0 + ac[j]);
        #pragma unroll
        for (int j = 0; j < 3; j++)
            cp16(base + A_BYTES + br[j] * RSB + bc[j] * 2,
                 Bp + (size_t)(n0 + br[j]) * DIM_ + k0 + bc[j]);
        CP_COMMIT();
    };

    float acc[4][6][4] = {};

    load_stage(0); load_stage(1); load_stage(2);

    for (int s = 0; s < NSTEP; s++) {
        if (s + 3 < NSTEP) {
            asm volatile("cp.async.wait_group 2;" ::: "memory");
            __syncthreads();
            load_stage(s + 3);
        } else if (s + 3 == NSTEP) {
            asm volatile("cp.async.wait_group 2;" ::: "memory");
            __syncthreads();
        } else if (s + 2 == NSTEP) {
            asm volatile("cp.async.wait_group 1;" ::: "memory");
            __syncthreads();
        } else {
            asm volatile("cp.async.wait_group 0;" ::: "memory");
            __syncthreads();
        }

        uint32_t abase = sb + (s & 3) * STAGE_B;
        uint32_t bbase = abase + A_BYTES;

        // load ALL fragments for both kk halves (14 ldsm), then 48 MMAs
        uint32_t af[2][4][4], bf[2][3][4];
        #pragma unroll
        for (int kk = 0; kk < 2; kk++) {
            #pragma unroll
            for (int mt = 0; mt < 4; mt++) {
                int r  = wm + mt * 16 + (lane & 15);
                int kc = kk * 16 + (lane >> 4) * 8;
                ldsm4(af[kk][mt], abase + r * RSB + kc * 2);
            }
            #pragma unroll
            for (int np = 0; np < 3; np++) {
                int n  = wn + np * 16 + (lane & 7) + ((lane >> 4) << 3);
                int kc = kk * 16 + ((lane >> 3) & 1) * 8;
                ldsm4(bf[kk][np], bbase + n * RSB + kc * 2);
            }
        }
        #pragma unroll
        for (int kk = 0; kk < 2; kk++)
            #pragma unroll
            for (int mt = 0; mt < 4; mt++)
                #pragma unroll
                for (int nt = 0; nt < 6; nt++)
                    mma_bf16(acc[mt][nt], af[kk][mt], &bf[kk][nt >> 1][(nt & 1) * 2]);
    }

    int crow0 = m0 + wm + (lane >> 2);
    int ccol0 = n0 + wn + (lane & 3) * 2;
    #pragma unroll
    for (int mt = 0; mt < 4; mt++) {
        #pragma unroll
        for (int half = 0; half < 2; half++) {
            int row = crow0 + mt * 16 + half * 8;
            #pragma unroll
            for (int nt = 0; nt < 6; nt++) {
                int col = ccol0 + nt * 8;
                float f0 = acc[mt][nt][half * 2]     + bp[col];
                float f1 = acc[mt][nt][half * 2 + 1] + bp[col + 1];
                if (MODE == 0) {
                    if (lgt) {
                        float2 o; o.x = f0; o.y = f1;
                        *(float2*)(g_logits + (size_t)row * NCAT + col) = o;
                    } else {
                        uint32_t pk;
                        asm("cvt.rn.bf16x2.f32 %0, %1, %2;" : "=r"(pk) : "f"(f1), "f"(f0));
                        *(uint32_t*)((__nv_bfloat16*)Cout + (size_t)row * ldcc + col) = pk;
                    }
                } else {
                    const float* qr = resid + (size_t)row * ldcc + col;
                    float2 o;
                    o.x = qr[0] + gamma[col]     * f0;
                    o.y = qr[1] + gamma[col + 1] * f1;
                    *(float2*)((float*)Cout + (size_t)row * ldcc + col) = o;
                }
            }
        }
    }
}

// ---------------- bilinear sampling: branchless, 1 uint2 load per corner ----------
__global__ __launch_bounds__(256) void sample_kernel(const float* __restrict__ refp)
{
    int w = blockIdx.x * 8 + (threadIdx.x >> 5);
    int lane = threadIdx.x & 31;
    int h  = w % HEADS_;
    int qi = w / HEADS_;
    int b  = qi >> 12;

    const float* lg = g_logits + (size_t)qi * NCAT;
    float x = (lane < 24) ? lg[48 + lane] : -1e30f;
    float m = x;
    #pragma unroll
    for (int o = 16; o; o >>= 1) m = fmaxf(m, __shfl_xor_sync(0xffffffffu, m, o));
    float e = (lane < 24) ? __expf(x - m) : 0.f;
    float ss = e;
    #pragma unroll
    for (int o = 16; o; o >>= 1) ss += __shfl_xor_sync(0xffffffffu, ss, o);
    float p_all = e / ss;
    float off = (lane < 8) ? lg[h * 8 + lane] : 0.f;
    float rx = refp[(size_t)qi * 2 + 0] * (float)HW_ - 0.5f;
    float ry = refp[(size_t)qi * 2 + 1] * (float)HW_ - 0.5f;

    float a0 = 0.f, a1 = 0.f, a2 = 0.f, a3 = 0.f;
    const uint2* vp = (const uint2*)(g_valb + (size_t)b * NQ_ * DIM_ + h * HD_) + lane;
    const int POS = DIM_ / 4;

    #pragma unroll
    for (int p = 0; p < POINTS_; p++) {
        float aw = __shfl_sync(0xffffffffu, p_all, h * POINTS_ + p);
        float xf = rx + __shfl_sync(0xffffffffu, off, p * 2);
        float yf = ry + __shfl_sync(0xffffffffu, off, p * 2 + 1);
        float x0f = floorf(xf), y0f = floorf(yf);
        float wx = xf - x0f, wy = yf - y0f;
        int x0 = (int)x0f, y0 = (int)y0f;
        #pragma unroll
        for (int dy = 0; dy < 2; dy++) {
            #pragma unroll
            for (int dx = 0; dx < 2; dx++) {
                int xi = x0 + dx, yi = y0 + dy;
                bool v = (xi >= 0) & (xi < HW_) & (yi >= 0) & (yi < HW_);
                int xc = min(max(xi, 0), HW_ - 1);
                int yc = min(max(yi, 0), HW_ - 1);
                float cw = aw * (dy ? wy : 1.f - wy) * (dx ? wx : 1.f - wx);
                cw = v ? cw : 0.f;
                uint2 q = vp[(yc * HW_ + xc) * POS];
                float2 f0 = __bfloat1622float2(*(__nv_bfloat162*)&q.x);
                float2 f1 = __bfloat1622float2(*(__nv_bfloat162*)&q.y);
                a0 = fmaf(cw, f0.x, a0);
                a1 = fmaf(cw, f0.y, a1);
                a2 = fmaf(cw, f1.x, a2);
                a3 = fmaf(cw, f1.y, a3);
            }
        }
    }
    uint2 pk;
    asm("cvt.rn.bf16x2.f32 %0, %1, %2;" : "=r"(pk.x) : "f"(a1), "f"(a0));
    asm("cvt.rn.bf16x2.f32 %0, %1, %2;" : "=r"(pk.y) : "f"(a3), "f"(a2));
    ((uint2*)(g_attnb + (size_t)qi * DIM_ + h * HD_))[lane] = pk;
}

// ---------------- launch ----------------
extern "C" void kernel_launch(void* const* d_in, const int* in_sizes, int n_in,
                              void* d_out, int out_size)
{
    const float* query = (const float*)d_in[0];
    const float* refp  = (const float*)d_in[1];
    const float* feat  = (const float*)d_in[2];
    const float* lnw   = (const float*)d_in[5];
    const float* lnb   = (const float*)d_in[6];
    const float* vpw   = (const float*)d_in[7];
    const float* vpb   = (const float*)d_in[8];
    const float* offw  = (const float*)d_in[9];
    const float* offb  = (const float*)d_in[10];
    const float* aww   = (const float*)d_in[11];
    const float* awb   = (const float*)d_in[12];
    const float* outw  = (const float*)d_in[13];
    const float* outb  = (const float*)d_in[14];
    const float* gamma = (const float*)d_in[15];
    float* out = (float*)d_out;

    __nv_bfloat16 *p_featb, *p_valb, *p_attnb, *p_vpwt, *p_outwt;
    cudaGetSymbolAddress((void**)&p_featb, g_featb);
    cudaGetSymbolAddress((void**)&p_valb,  g_valb);
    cudaGetSymbolAddress((void**)&p_attnb, g_attnb);
    cudaGetSymbolAddress((void**)&p_vpwt,  g_vpwt);
    cudaGetSymbolAddress((void**)&p_outwt, g_outwt);

    const int SMEM = 4 * STAGE_B;
    cudaFuncSetAttribute(gemm_bf16<0>, cudaFuncAttributeMaxDynamicSharedMemorySize, SMEM);
    cudaFuncSetAttribute(gemm_bf16<1>, cudaFuncAttributeMaxDynamicSharedMemorySize, SMEM);

    dim3 g0(DIM_ / 96 + 1, NROWS_ / 128);   // (9, 64): 8 value tiles + 1 logits tile
    dim3 g1(DIM_ / 96, NROWS_ / 128);       // (8, 64)

    prologue_kernel<<<PB_TOT, 384>>>(query, lnw, lnb, feat, vpw, outw,
                                     offw, offb, aww, awb);
    gemm_bf16<0><<<g0, 128, SMEM>>>(p_featb, p_vpwt, vpb, p_valb, DIM_, nullptr, nullptr);
    sample_kernel<<<NROWS_ * HEADS_ / 8, 256>>>(refp);
    gemm_bf16<1><<<g1, 128, SMEM>>>(p_attnb, p_outwt, outb, out, DIM_, query, gamma);
}

// round 11
// speedup vs baseline: 6.2752x; 1.0418x over previous
#include <cuda_runtime.h>
#include <cuda_bf16.h>
#include <math.h>
#include <cstdint>

#define BS_    2
#define NQ_    4096
#define DIM_   768
#define HEADS_ 6
#define POINTS_ 4
#define HD_    128
#define HW_    64
#define NROWS_ (BS_*NQ_)   // 8192
#define NCAT   96

// ---------------- scratch ----------------
__device__ __align__(128) __nv_bfloat16 g_qnb  [NROWS_*DIM_];
__device__ __align__(128) __nv_bfloat16 g_featb[NROWS_*DIM_];
__device__ __align__(128) __nv_bfloat16 g_valb [NROWS_*DIM_];
__device__ __align__(128) __nv_bfloat16 g_attnb[NROWS_*DIM_];
__device__ __align__(128) __nv_bfloat16 g_vpwt [DIM_*DIM_];
__device__ __align__(128) __nv_bfloat16 g_outwt[DIM_*DIM_];
__device__ __align__(128) __nv_bfloat16 g_catwt[NCAT*DIM_];
__device__ __align__(128) float g_bcat[NCAT];
__device__ __align__(128) float g_logits[NROWS_*NCAT];

// ================= PTX helpers =================
__device__ __forceinline__ uint32_t smem_u32(const void* p) {
    uint32_t a;
    asm("{ .reg .u64 t; cvta.to.shared.u64 t, %1; cvt.u32.u64 %0, t; }" : "=r"(a) : "l"(p));
    return a;
}
__device__ __forceinline__ void cp16(uint32_t dst, const void* src) {
    asm volatile("cp.async.cg.shared.global [%0], [%1], 16;" :: "r"(dst), "l"(src));
}
#define CP_COMMIT() asm volatile("cp.async.commit_group;" ::: "memory")

__device__ __forceinline__ void ldsm4(uint32_t* r, uint32_t addr) {
    asm volatile("ldmatrix.sync.aligned.m8n8.x4.shared.b16 {%0,%1,%2,%3}, [%4];"
                 : "=r"(r[0]), "=r"(r[1]), "=r"(r[2]), "=r"(r[3]) : "r"(addr));
}
__device__ __forceinline__ void mma_bf16(float* c, const uint32_t* a, const uint32_t* b) {
    asm volatile("mma.sync.aligned.m16n8k16.row.col.f32.bf16.bf16.f32 "
                 "{%0,%1,%2,%3}, {%4,%5,%6,%7}, {%8,%9}, {%0,%1,%2,%3};"
                 : "+f"(c[0]), "+f"(c[1]), "+f"(c[2]), "+f"(c[3])
                 : "r"(a[0]), "r"(a[1]), "r"(a[2]), "r"(a[3]), "r"(b[0]), "r"(b[1]));
}

// ---------------- fused prologue: ln | convA | convT x2 | convW ----------------
#define PB_LN   (NROWS_/8)                   // 1024 (warp-per-row, 8 rows/block)
#define PB_CA   (NROWS_*DIM_/4/768)          // 2048 (2 float4 per thread)
#define PB_CT   ((DIM_/32)*(DIM_/32)*2)      // 1152
#define PB_CW   ((NCAT*DIM_)/384)            // 192
#define PB_TOT  (PB_LN + PB_CA + PB_CT + PB_CW)

__global__ __launch_bounds__(384) void prologue_kernel(
    const float* __restrict__ query,
    const float* __restrict__ lnw, const float* __restrict__ lnb,
    const float* __restrict__ feat,
    const float* __restrict__ vpw, const float* __restrict__ outw,
    const float* __restrict__ offw, const float* __restrict__ offb,
    const float* __restrict__ aww,  const float* __restrict__ awb)
{
    __shared__ __align__(16) float sh[32 * 33];
    int bid = blockIdx.x;
    int tid = threadIdx.x;

    if (bid < PB_LN) {
        // ---- layernorm: one warp per row, 12 warps -> first 8 used per block? ----
        // 384 threads = 12 warps; use all 12? rows = bid*12.. no: PB_LN sized for 8.
        int warp = tid >> 5, lane = tid & 31;
        if (warp < 8) {
            int row = bid * 8 + warp;
            const float4* x4 = (const float4*)(query + (size_t)row * DIM_);
            float4 v[6];
            float s = 0.f;
            #pragma unroll
            for (int j = 0; j < 6; j++) {
                v[j] = x4[lane + j * 32];
                s += v[j].x + v[j].y + v[j].z + v[j].w;
            }
            #pragma unroll
            for (int o = 16; o; o >>= 1) s += __shfl_xor_sync(0xffffffffu, s, o);
            float mean = s * (1.f / DIM_);
            float var = 0.f;
            #pragma unroll
            for (int j = 0; j < 6; j++) {
                float d0 = v[j].x - mean, d1 = v[j].y - mean;
                float d2 = v[j].z - mean, d3 = v[j].w - mean;
                var += d0 * d0 + d1 * d1 + d2 * d2 + d3 * d3;
            }
            #pragma unroll
            for (int o = 16; o; o >>= 1) var += __shfl_xor_sync(0xffffffffu, var, o);
            float rstd = rsqrtf(var * (1.f / DIM_) + 1e-6f);
            const float4* w4 = (const float4*)lnw;
            const float4* b4 = (const float4*)lnb;
            uint2* o2 = (uint2*)(g_qnb + (size_t)row * DIM_);
            #pragma unroll
            for (int j = 0; j < 6; j++) {
                float4 ww = w4[lane + j * 32];
                float4 bb = b4[lane + j * 32];
                float f0 = (v[j].x - mean) * rstd * ww.x + bb.x;
                float f1 = (v[j].y - mean) * rstd * ww.y + bb.y;
                float f2 = (v[j].z - mean) * rstd * ww.z + bb.z;
                float f3 = (v[j].w - mean) * rstd * ww.w + bb.w;
                uint2 pk;
                asm("cvt.rn.bf16x2.f32 %0, %1, %2;" : "=r"(pk.x) : "f"(f1), "f"(f0));
                asm("cvt.rn.bf16x2.f32 %0, %1, %2;" : "=r"(pk.y) : "f"(f3), "f"(f2));
                o2[lane + j * 32] = pk;
            }
        }
    } else if (bid < PB_LN + PB_CA) {
        // ---- feat -> bf16, 2 float4 per thread ----
        int base = (bid - PB_LN) * 768 + tid;
        #pragma unroll
        for (int u = 0; u < 2; u++) {
            int i = base + u * 384;
            float4 v = ((const float4*)feat)[i];
            uint32_t lo, hi;
            asm("cvt.rn.bf16x2.f32 %0, %1, %2;" : "=r"(lo) : "f"(v.y), "f"(v.x));
            asm("cvt.rn.bf16x2.f32 %0, %1, %2;" : "=r"(hi) : "f"(v.w), "f"(v.z));
            ((uint2*)g_featb)[i] = make_uint2(lo, hi);
        }
    } else if (bid < PB_LN + PB_CA + PB_CT) {
        int t = bid - (PB_LN + PB_CA);
        int z = t / 576;
        int rem = t % 576;
        const float* W    = z ? outw : vpw;
        __nv_bfloat16* Wt = z ? g_outwt : g_vpwt;
        int bx = (rem % 24) * 32, by = (rem / 24) * 32;
        int tx = tid & 31, ty = (tid >> 5);
        if (ty < 8) {
            #pragma unroll
            for (int i = 0; i < 32; i += 8)
                sh[(ty + i) * 33 + tx] = W[(size_t)(by + ty + i) * DIM_ + bx + tx];
        }
        __syncthreads();
        if (ty < 8) {
            #pragma unroll
            for (int i = 0; i < 32; i += 8)
                Wt[(size_t)(bx + ty + i) * DIM_ + by + tx] =
                    __float2bfloat16(sh[tx * 33 + ty + i]);
        }
    } else {
        int lb = bid - (PB_LN + PB_CA + PB_CT);
        int i = lb * 384 + tid;
        int c = i / DIM_, k = i % DIM_;
        float v = 0.f;
        if (c < 48)      v = offw[(size_t)k * 48 + c];
        else if (c < 72) v = aww[(size_t)k * 24 + (c - 48)];
        g_catwt[i] = __float2bfloat16(v);
        if (lb == 0 && tid < NCAT)
            g_bcat[tid] = (tid < 48) ? offb[tid] : (tid < 72 ? awb[tid - 48] : 0.f);
    }
}

// ---------------- HMMA bf16 GEMM: CTA 128x96, 4 warps 64x48, KC=64, 3 stages -------
#define KC       64
#define RSB      144              // 64 bf16 = 128 B + 16 pad; 36-word stride, ldsm conflict-free
#define A_BYTES  (128 * RSB)      // 18432
#define B_BYTES  (96 * RSB)       // 13824
#define STAGE_B  (A_BYTES + B_BYTES)  // 32256
#define NSTEP    (DIM_ / KC)      // 12

template <int MODE>
__global__ __launch_bounds__(128, 2) void gemm_bf16(
    const __nv_bfloat16* __restrict__ A, const __nv_bfloat16* __restrict__ Bt,
    const float* __restrict__ bias, void* __restrict__ Cout, int ldc,
    const float* __restrict__ resid, const float* __restrict__ gamma)
{
    extern __shared__ __align__(128) char dsm[];
    uint32_t sb = smem_u32(dsm);
    int tid = threadIdx.x, wid = tid >> 5, lane = tid & 31;
    int m0 = blockIdx.y * 128;
    int wm = (wid & 1) * 64;
    int wn = (wid >> 1) * 48;

    bool lgt = (MODE == 0) && (blockIdx.x == 8);
    const __nv_bfloat16* Ap  = lgt ? g_qnb   : A;
    const __nv_bfloat16* Bp  = lgt ? g_catwt : Bt;
    const float*         bp  = lgt ? g_bcat  : bias;
    int n0   = lgt ? 0 : blockIdx.x * 96;
    int ldcc = lgt ? NCAT : ldc;

    // cp.async: A 1024 chunks (8/thread), B 768 chunks (6/thread); chunk=16B
    int ar[8], ac[8];
    #pragma unroll
    for (int j = 0; j < 8; j++) {
        int id = j * 128 + tid;
        ar[j] = id >> 3;
        ac[j] = (id & 7) * 8;     // bf16 element offset within 64-wide row
    }
    int br[6], bc[6];
    #pragma unroll
    for (int j = 0; j < 6; j++) {
        int id = j * 128 + tid;
        br[j] = id >> 3;
        bc[j] = (id & 7) * 8;
    }

    auto load_stage = [&](int s) {
        uint32_t base = sb + (s % 3) * STAGE_B;
        int k0 = s * KC;
        #pragma unroll
        for (int j = 0; j < 8; j++)
            cp16(base + ar[j] * RSB + ac[j] * 2,
                 Ap + (size_t)(m0 + ar[j]) * DIM_ + k0 + ac[j]);
        #pragma unroll
        for (int j = 0; j < 6; j++)
            cp16(base + A_BYTES + br[j] * RSB + bc[j] * 2,
                 Bp + (size_t)(n0 + br[j]) * DIM_ + k0 + bc[j]);
        CP_COMMIT();
    };

    float acc[4][6][4] = {};

    load_stage(0); load_stage(1);

    for (int s = 0; s < NSTEP; s++) {
        if (s + 2 < NSTEP) {
            asm volatile("cp.async.wait_group 1;" ::: "memory");
            __syncthreads();
            load_stage(s + 2);
        } else if (s + 1 < NSTEP) {
            asm volatile("cp.async.wait_group 1;" ::: "memory");
            __syncthreads();
        } else {
            asm volatile("cp.async.wait_group 0;" ::: "memory");
            __syncthreads();
        }

        uint32_t abase = sb + (s % 3) * STAGE_B;
        uint32_t bbase = abase + A_BYTES;
        #pragma unroll
        for (int kk = 0; kk < 4; kk++) {
            uint32_t af[4][4], bf[3][4];
            #pragma unroll
            for (int mt = 0; mt < 4; mt++) {
                int r  = wm + mt * 16 + (lane & 15);
                int kc = kk * 16 + (lane >> 4) * 8;
                ldsm4(af[mt], abase + r * RSB + kc * 2);
            }
            #pragma unroll
            for (int np = 0; np < 3; np++) {
                int n  = wn + np * 16 + (lane & 7) + ((lane >> 4) << 3);
                int kc = kk * 16 + ((lane >> 3) & 1) * 8;
                ldsm4(bf[np], bbase + n * RSB + kc * 2);
            }
            #pragma unroll
            for (int mt = 0; mt < 4; mt++)
                #pragma unroll
                for (int nt = 0; nt < 6; nt++)
                    mma_bf16(acc[mt][nt], af[mt], &bf[nt >> 1][(nt & 1) * 2]);
        }
    }

    int crow0 = m0 + wm + (lane >> 2);
    int ccol0 = n0 + wn + (lane & 3) * 2;
    #pragma unroll
    for (int mt = 0; mt < 4; mt++) {
        #pragma unroll
        for (int half = 0; half < 2; half++) {
            int row = crow0 + mt * 16 + half * 8;
            #pragma unroll
            for (int nt = 0; nt < 6; nt++) {
                int col = ccol0 + nt * 8;
                float f0 = acc[mt][nt][half * 2]     + bp[col];
                float f1 = acc[mt][nt][half * 2 + 1] + bp[col + 1];
                if (MODE == 0) {
                    if (lgt) {
                        float2 o; o.x = f0; o.y = f1;
                        *(float2*)(g_logits + (size_t)row * NCAT + col) = o;
                    } else {
                        uint32_t pk;
                        asm("cvt.rn.bf16x2.f32 %0, %1, %2;" : "=r"(pk) : "f"(f1), "f"(f0));
                        *(uint32_t*)((__nv_bfloat16*)Cout + (size_t)row * ldcc + col) = pk;
                    }
                } else {
                    const float* qr = resid + (size_t)row * ldcc + col;
                    float2 o;
                    o.x = qr[0] + gamma[col]     * f0;
                    o.y = qr[1] + gamma[col + 1] * f1;
                    *(float2*)((float*)Cout + (size_t)row * ldcc + col) = o;
                }
            }
        }
    }
}

// ---------------- bilinear sampling: branchless, 1 uint2 load per corner ----------
__global__ __launch_bounds__(256) void sample_kernel(const float* __restrict__ refp)
{
    int w = blockIdx.x * 8 + (threadIdx.x >> 5);
    int lane = threadIdx.x & 31;
    int h  = w % HEADS_;
    int qi = w / HEADS_;
    int b  = qi >> 12;

    const float* lg = g_logits + (size_t)qi * NCAT;
    float x = (lane < 24) ? lg[48 + lane] : -1e30f;
    float m = x;
    #pragma unroll
    for (int o = 16; o; o >>= 1) m = fmaxf(m, __shfl_xor_sync(0xffffffffu, m, o));
    float e = (lane < 24) ? __expf(x - m) : 0.f;
    float ss = e;
    #pragma unroll
    for (int o = 16; o; o >>= 1) ss += __shfl_xor_sync(0xffffffffu, ss, o);
    float p_all = e / ss;
    float off = (lane < 8) ? lg[h * 8 + lane] : 0.f;
    float rx = refp[(size_t)qi * 2 + 0] * (float)HW_ - 0.5f;
    float ry = refp[(size_t)qi * 2 + 1] * (float)HW_ - 0.5f;

    float a0 = 0.f, a1 = 0.f, a2 = 0.f, a3 = 0.f;
    const uint2* vp = (const uint2*)(g_valb + (size_t)b * NQ_ * DIM_ + h * HD_) + lane;
    const int POS = DIM_ / 4;

    #pragma unroll
    for (int p = 0; p < POINTS_; p++) {
        float aw = __shfl_sync(0xffffffffu, p_all, h * POINTS_ + p);
        float xf = rx + __shfl_sync(0xffffffffu, off, p * 2);
        float yf = ry + __shfl_sync(0xffffffffu, off, p * 2 + 1);
        float x0f = floorf(xf), y0f = floorf(yf);
        float wx = xf - x0f, wy = yf - y0f;
        int x0 = (int)x0f, y0 = (int)y0f;
        #pragma unroll
        for (int dy = 0; dy < 2; dy++) {
            #pragma unroll
            for (int dx = 0; dx < 2; dx++) {
                int xi = x0 + dx, yi = y0 + dy;
                bool v = (xi >= 0) & (xi < HW_) & (yi >= 0) & (yi < HW_);
                int xc = min(max(xi, 0), HW_ - 1);
                int yc = min(max(yi, 0), HW_ - 1);
                float cw = aw * (dy ? wy : 1.f - wy) * (dx ? wx : 1.f - wx);
                cw = v ? cw : 0.f;
                uint2 q = vp[(yc * HW_ + xc) * POS];
                float2 f0 = __bfloat1622float2(*(__nv_bfloat162*)&q.x);
                float2 f1 = __bfloat1622float2(*(__nv_bfloat162*)&q.y);
                a0 = fmaf(cw, f0.x, a0);
                a1 = fmaf(cw, f0.y, a1);
                a2 = fmaf(cw, f1.x, a2);
                a3 = fmaf(cw, f1.y, a3);
            }
        }
    }
    uint2 pk;
    asm("cvt.rn.bf16x2.f32 %0, %1, %2;" : "=r"(pk.x) : "f"(a1), "f"(a0));
    asm("cvt.rn.bf16x2.f32 %0, %1, %2;" : "=r"(pk.y) : "f"(a3), "f"(a2));
    ((uint2*)(g_attnb + (size_t)qi * DIM_ + h * HD_))[lane] = pk;
}

// ---------------- launch ----------------
extern "C" void kernel_launch(void* const* d_in, const int* in_sizes, int n_in,
                              void* d_out, int out_size)
{
    const float* query = (const float*)d_in[0];
    const float* refp  = (const float*)d_in[1];
    const float* feat  = (const float*)d_in[2];
    const float* lnw   = (const float*)d_in[5];
    const float* lnb   = (const float*)d_in[6];
    const float* vpw   = (const float*)d_in[7];
    const float* vpb   = (const float*)d_in[8];
    const float* offw  = (const float*)d_in[9];
    const float* offb  = (const float*)d_in[10];
    const float* aww   = (const float*)d_in[11];
    const float* awb   = (const float*)d_in[12];
    const float* outw  = (const float*)d_in[13];
    const float* outb  = (const float*)d_in[14];
    const float* gamma = (const float*)d_in[15];
    float* out = (float*)d_out;

    __nv_bfloat16 *p_featb, *p_valb, *p_attnb, *p_vpwt, *p_outwt;
    cudaGetSymbolAddress((void**)&p_featb, g_featb);
    cudaGetSymbolAddress((void**)&p_valb,  g_valb);
    cudaGetSymbolAddress((void**)&p_attnb, g_attnb);
    cudaGetSymbolAddress((void**)&p_vpwt,  g_vpwt);
    cudaGetSymbolAddress((void**)&p_outwt, g_outwt);

    const int SMEM = 3 * STAGE_B;   // 96768
    cudaFuncSetAttribute(gemm_bf16<0>, cudaFuncAttributeMaxDynamicSharedMemorySize, SMEM);
    cudaFuncSetAttribute(gemm_bf16<1>, cudaFuncAttributeMaxDynamicSharedMemorySize, SMEM);

    dim3 g0(DIM_ / 96 + 1, NROWS_ / 128);   // (9, 64)
    dim3 g1(DIM_ / 96, NROWS_ / 128);       // (8, 64)

    prologue_kernel<<<PB_TOT, 384>>>(query, lnw, lnb, feat, vpw, outw,
                                     offw, offb, aww, awb);
    gemm_bf16<0><<<g0, 128, SMEM>>>(p_featb, p_vpwt, vpb, p_valb, DIM_, nullptr, nullptr);
    sample_kernel<<<NROWS_ * HEADS_ / 8, 256>>>(refp);
    gemm_bf16<1><<<g1, 128, SMEM>>>(p_attnb, p_outwt, outb, out, DIM_, query, gamma);
}

// round 12
// speedup vs baseline: 6.2783x; 1.0005x over previous
#include <cuda_runtime.h>
#include <cuda_bf16.h>
#include <math.h>
#include <cstdint>

#define BS_    2
#define NQ_    4096
#define DIM_   768
#define HEADS_ 6
#define POINTS_ 4
#define HD_    128
#define HW_    64
#define NROWS_ (BS_*NQ_)   // 8192
#define NCAT   128         // padded offset/aw projection width (72 -> 128)

// ---------------- scratch ----------------
__device__ __align__(128) __nv_bfloat16 g_qnb  [NROWS_*DIM_];
__device__ __align__(128) __nv_bfloat16 g_featb[NROWS_*DIM_];
__device__ __align__(128) __nv_bfloat16 g_valb [NROWS_*DIM_];
__device__ __align__(128) __nv_bfloat16 g_attnb[NROWS_*DIM_];
__device__ __align__(128) __nv_bfloat16 g_vpwt [DIM_*DIM_];
__device__ __align__(128) __nv_bfloat16 g_outwt[DIM_*DIM_];
__device__ __align__(128) __nv_bfloat16 g_catwt[NCAT*DIM_];
__device__ __align__(128) float g_bcat[NCAT];
__device__ __align__(128) float g_logits[NROWS_*NCAT];

// ================= PTX helpers =================
__device__ __forceinline__ uint32_t smem_u32(const void* p) {
    uint32_t a;
    asm("{ .reg .u64 t; cvta.to.shared.u64 t, %1; cvt.u32.u64 %0, t; }" : "=r"(a) : "l"(p));
    return a;
}
__device__ __forceinline__ void cp16(uint32_t dst, const void* src) {
    asm volatile("cp.async.cg.shared.global [%0], [%1], 16;" :: "r"(dst), "l"(src));
}
#define CP_COMMIT() asm volatile("cp.async.commit_group;" ::: "memory")

__device__ __forceinline__ void ldsm4(uint32_t* r, uint32_t addr) {
    asm volatile("ldmatrix.sync.aligned.m8n8.x4.shared.b16 {%0,%1,%2,%3}, [%4];"
                 : "=r"(r[0]), "=r"(r[1]), "=r"(r[2]), "=r"(r[3]) : "r"(addr));
}
__device__ __forceinline__ void mma_bf16(float* c, const uint32_t* a, const uint32_t* b) {
    asm volatile("mma.sync.aligned.m16n8k16.row.col.f32.bf16.bf16.f32 "
                 "{%0,%1,%2,%3}, {%4,%5,%6,%7}, {%8,%9}, {%0,%1,%2,%3};"
                 : "+f"(c[0]), "+f"(c[1]), "+f"(c[2]), "+f"(c[3])
                 : "r"(a[0]), "r"(a[1]), "r"(a[2]), "r"(a[3]), "r"(b[0]), "r"(b[1]));
}

// ---------------- fused prologue: ln | convA | convT x2 | convW ----------------
#define PB_LN   (NROWS_/8)                   // 1024
#define PB_CA   (NROWS_*DIM_/4/768)          // 2048
#define PB_CT   ((DIM_/32)*(DIM_/32)*2)      // 1152
#define PB_CW   ((NCAT*DIM_)/384)            // 256
#define PB_TOT  (PB_LN + PB_CA + PB_CT + PB_CW)

__global__ __launch_bounds__(384) void prologue_kernel(
    const float* __restrict__ query,
    const float* __restrict__ lnw, const float* __restrict__ lnb,
    const float* __restrict__ feat,
    const float* __restrict__ vpw, const float* __restrict__ outw,
    const float* __restrict__ offw, const float* __restrict__ offb,
    const float* __restrict__ aww,  const float* __restrict__ awb)
{
    __shared__ __align__(16) float sh[32 * 33];
    int bid = blockIdx.x;
    int tid = threadIdx.x;

    if (bid < PB_LN) {
        int warp = tid >> 5, lane = tid & 31;
        if (warp < 8) {
            int row = bid * 8 + warp;
            const float4* x4 = (const float4*)(query + (size_t)row * DIM_);
            float4 v[6];
            float s = 0.f;
            #pragma unroll
            for (int j = 0; j < 6; j++) {
                v[j] = x4[lane + j * 32];
                s += v[j].x + v[j].y + v[j].z + v[j].w;
            }
            #pragma unroll
            for (int o = 16; o; o >>= 1) s += __shfl_xor_sync(0xffffffffu, s, o);
            float mean = s * (1.f / DIM_);
            float var = 0.f;
            #pragma unroll
            for (int j = 0; j < 6; j++) {
                float d0 = v[j].x - mean, d1 = v[j].y - mean;
                float d2 = v[j].z - mean, d3 = v[j].w - mean;
                var += d0 * d0 + d1 * d1 + d2 * d2 + d3 * d3;
            }
            #pragma unroll
            for (int o = 16; o; o >>= 1) var += __shfl_xor_sync(0xffffffffu, var, o);
            float rstd = rsqrtf(var * (1.f / DIM_) + 1e-6f);
            const float4* w4 = (const float4*)lnw;
            const float4* b4 = (const float4*)lnb;
            uint2* o2 = (uint2*)(g_qnb + (size_t)row * DIM_);
            #pragma unroll
            for (int j = 0; j < 6; j++) {
                float4 ww = w4[lane + j * 32];
                float4 bb = b4[lane + j * 32];
                float f0 = (v[j].x - mean) * rstd * ww.x + bb.x;
                float f1 = (v[j].y - mean) * rstd * ww.y + bb.y;
                float f2 = (v[j].z - mean) * rstd * ww.z + bb.z;
                float f3 = (v[j].w - mean) * rstd * ww.w + bb.w;
                uint2 pk;
                asm("cvt.rn.bf16x2.f32 %0, %1, %2;" : "=r"(pk.x) : "f"(f1), "f"(f0));
                asm("cvt.rn.bf16x2.f32 %0, %1, %2;" : "=r"(pk.y) : "f"(f3), "f"(f2));
                o2[lane + j * 32] = pk;
            }
        }
    } else if (bid < PB_LN + PB_CA) {
        int base = (bid - PB_LN) * 768 + tid;
        #pragma unroll
        for (int u = 0; u < 2; u++) {
            int i = base + u * 384;
            float4 v = ((const float4*)feat)[i];
            uint32_t lo, hi;
            asm("cvt.rn.bf16x2.f32 %0, %1, %2;" : "=r"(lo) : "f"(v.y), "f"(v.x));
            asm("cvt.rn.bf16x2.f32 %0, %1, %2;" : "=r"(hi) : "f"(v.w), "f"(v.z));
            ((uint2*)g_featb)[i] = make_uint2(lo, hi);
        }
    } else if (bid < PB_LN + PB_CA + PB_CT) {
        int t = bid - (PB_LN + PB_CA);
        int z = t / 576;
        int rem = t % 576;
        const float* W    = z ? outw : vpw;
        __nv_bfloat16* Wt = z ? g_outwt : g_vpwt;
        int bx = (rem % 24) * 32, by = (rem / 24) * 32;
        int tx = tid & 31, ty = (tid >> 5);
        if (ty < 8) {
            #pragma unroll
            for (int i = 0; i < 32; i += 8)
                sh[(ty + i) * 33 + tx] = W[(size_t)(by + ty + i) * DIM_ + bx + tx];
        }
        __syncthreads();
        if (ty < 8) {
            #pragma unroll
            for (int i = 0; i < 32; i += 8)
                Wt[(size_t)(bx + ty + i) * DIM_ + by + tx] =
                    __float2bfloat16(sh[tx * 33 + ty + i]);
        }
    } else {
        int lb = bid - (PB_LN + PB_CA + PB_CT);
        int i = lb * 384 + tid;
        int c = i / DIM_, k = i % DIM_;
        float v = 0.f;
        if (c < 48)      v = offw[(size_t)k * 48 + c];
        else if (c < 72) v = aww[(size_t)k * 24 + (c - 48)];
        g_catwt[i] = __float2bfloat16(v);
        if (lb == 0 && tid < NCAT)
            g_bcat[tid] = (tid < 48) ? offb[tid] : (tid < 72 ? awb[tid - 48] : 0.f);
    }
}

// ------- HMMA bf16 GEMM: CTA 128x64, 4 warps 64x32, KC=64, 3 stages, --------------
// ------- explicit double-buffered fragments (WAR-free kk pipeline) ----------------
#define KC       64
#define RSB      144
#define A_BYTES  (128 * RSB)          // 18432
#define B_BYTES  (64 * RSB)           // 9216
#define STAGE_B  (A_BYTES + B_BYTES)  // 27648
#define NSTEP    (DIM_ / KC)          // 12
#define NVT      (DIM_ / 64)          // 12 value n-tiles

template <int MODE>
__global__ __launch_bounds__(128, 2) void gemm_bf16(
    const __nv_bfloat16* __restrict__ A, const __nv_bfloat16* __restrict__ Bt,
    const float* __restrict__ bias, void* __restrict__ Cout, int ldc,
    const float* __restrict__ resid, const float* __restrict__ gamma)
{
    extern __shared__ __align__(128) char dsm[];
    uint32_t sb = smem_u32(dsm);
    int tid = threadIdx.x, wid = tid >> 5, lane = tid & 31;
    int m0 = blockIdx.y * 128;
    int wm = (wid & 1) * 64;
    int wn = (wid >> 1) * 32;

    bool lgt = (MODE == 0) && ((int)blockIdx.x >= NVT);
    const __nv_bfloat16* Ap  = lgt ? g_qnb   : A;
    const __nv_bfloat16* Bp  = lgt ? g_catwt : Bt;
    const float*         bp  = lgt ? g_bcat  : bias;
    int n0   = lgt ? ((int)blockIdx.x - NVT) * 64 : blockIdx.x * 64;
    int ldcc = lgt ? NCAT : ldc;

    // cp.async: A 1024 chunks (8/thread), B 512 chunks (4/thread); chunk = 16 B
    int ar[8], ac[8];
    #pragma unroll
    for (int j = 0; j < 8; j++) {
        int id = j * 128 + tid;
        ar[j] = id >> 3;
        ac[j] = (id & 7) * 8;
    }
    int br[4], bc[4];
    #pragma unroll
    for (int j = 0; j < 4; j++) {
        int id = j * 128 + tid;
        br[j] = id >> 3;
        bc[j] = (id & 7) * 8;
    }

    auto load_stage = [&](int s) {
        uint32_t base = sb + (s % 3) * STAGE_B;
        int k0 = s * KC;
        #pragma unroll
        for (int j = 0; j < 8; j++)
            cp16(base + ar[j] * RSB + ac[j] * 2,
                 Ap + (size_t)(m0 + ar[j]) * DIM_ + k0 + ac[j]);
        #pragma unroll
        for (int j = 0; j < 4; j++)
            cp16(base + A_BYTES + br[j] * RSB + bc[j] * 2,
                 Bp + (size_t)(n0 + br[j]) * DIM_ + k0 + bc[j]);
        CP_COMMIT();
    };

    // fragment addresses (kk-dependent part added at use)
    int a_r  = wm + (lane & 15);
    int a_k  = (lane >> 4) * 8;
    int b_n  = wn + (lane & 7) + ((lane >> 4) << 3);
    int b_k  = ((lane >> 3) & 1) * 8;

    float acc[4][4][4] = {};
    uint32_t af[2][4][4], bf[2][2][4];

    auto load_frags = [&](uint32_t abase, uint32_t bbase, int kk, int buf) {
        #pragma unroll
        for (int mt = 0; mt < 4; mt++)
            ldsm4(af[buf][mt], abase + (a_r + mt * 16) * RSB + (kk * 16 + a_k) * 2);
        #pragma unroll
        for (int np = 0; np < 2; np++)
            ldsm4(bf[buf][np], bbase + (b_n + np * 16) * RSB + (kk * 16 + b_k) * 2);
    };
    auto do_mma = [&](int buf) {
        #pragma unroll
        for (int mt = 0; mt < 4; mt++)
            #pragma unroll
            for (int nt = 0; nt < 4; nt++)
                mma_bf16(acc[mt][nt], af[buf][mt], &bf[buf][nt >> 1][(nt & 1) * 2]);
    };

    load_stage(0); load_stage(1);

    for (int s = 0; s < NSTEP; s++) {
        if (s + 2 < NSTEP) {
            asm volatile("cp.async.wait_group 1;" ::: "memory");
            __syncthreads();
            load_stage(s + 2);
        } else if (s + 1 < NSTEP) {
            asm volatile("cp.async.wait_group 1;" ::: "memory");
            __syncthreads();
        } else {
            asm volatile("cp.async.wait_group 0;" ::: "memory");
            __syncthreads();
        }

        uint32_t abase = sb + (s % 3) * STAGE_B;
        uint32_t bbase = abase + A_BYTES;

        load_frags(abase, bbase, 0, 0);
        #pragma unroll
        for (int kk = 0; kk < 4; kk++) {
            if (kk < 3) load_frags(abase, bbase, kk + 1, (kk + 1) & 1);
            do_mma(kk & 1);
        }
    }

    int crow0 = m0 + wm + (lane >> 2);
    int ccol0 = n0 + wn + (lane & 3) * 2;
    #pragma unroll
    for (int mt = 0; mt < 4; mt++) {
        #pragma unroll
        for (int half = 0; half < 2; half++) {
            int row = crow0 + mt * 16 + half * 8;
            #pragma unroll
            for (int nt = 0; nt < 4; nt++) {
                int col = ccol0 + nt * 8;
                float f0 = acc[mt][nt][half * 2]     + bp[col];
                float f1 = acc[mt][nt][half * 2 + 1] + bp[col + 1];
                if (MODE == 0) {
                    if (lgt) {
                        float2 o; o.x = f0; o.y = f1;
                        *(float2*)(g_logits + (size_t)row * NCAT + col) = o;
                    } else {
                        uint32_t pk;
                        asm("cvt.rn.bf16x2.f32 %0, %1, %2;" : "=r"(pk) : "f"(f1), "f"(f0));
                        *(uint32_t*)((__nv_bfloat16*)Cout + (size_t)row * ldcc + col) = pk;
                    }
                } else {
                    const float* qr = resid + (size_t)row * ldcc + col;
                    float2 o;
                    o.x = qr[0] + gamma[col]     * f0;
                    o.y = qr[1] + gamma[col + 1] * f1;
                    *(float2*)((float*)Cout + (size_t)row * ldcc + col) = o;
                }
            }
        }
    }
}

// ---------------- bilinear sampling: branchless, 1 uint2 load per corner ----------
__global__ __launch_bounds__(256) void sample_kernel(const float* __restrict__ refp)
{
    int w = blockIdx.x * 8 + (threadIdx.x >> 5);
    int lane = threadIdx.x & 31;
    int h  = w % HEADS_;
    int qi = w / HEADS_;
    int b  = qi >> 12;

    const float* lg = g_logits + (size_t)qi * NCAT;
    float x = (lane < 24) ? lg[48 + lane] : -1e30f;
    float m = x;
    #pragma unroll
    for (int o = 16; o; o >>= 1) m = fmaxf(m, __shfl_xor_sync(0xffffffffu, m, o));
    float e = (lane < 24) ? __expf(x - m) : 0.f;
    float ss = e;
    #pragma unroll
    for (int o = 16; o; o >>= 1) ss += __shfl_xor_sync(0xffffffffu, ss, o);
    float p_all = e / ss;
    float off = (lane < 8) ? lg[h * 8 + lane] : 0.f;
    float rx = refp[(size_t)qi * 2 + 0] * (float)HW_ - 0.5f;
    float ry = refp[(size_t)qi * 2 + 1] * (float)HW_ - 0.5f;

    float a0 = 0.f, a1 = 0.f, a2 = 0.f, a3 = 0.f;
    const uint2* vp = (const uint2*)(g_valb + (size_t)b * NQ_ * DIM_ + h * HD_) + lane;
    const int POS = DIM_ / 4;

    #pragma unroll
    for (int p = 0; p < POINTS_; p++) {
        float aw = __shfl_sync(0xffffffffu, p_all, h * POINTS_ + p);
        float xf = rx + __shfl_sync(0xffffffffu, off, p * 2);
        float yf = ry + __shfl_sync(0xffffffffu, off, p * 2 + 1);
        float x0f = floorf(xf), y0f = floorf(yf);
        float wx = xf - x0f, wy = yf - y0f;
        int x0 = (int)x0f, y0 = (int)y0f;
        #pragma unroll
        for (int dy = 0; dy < 2; dy++) {
            #pragma unroll
            for (int dx = 0; dx < 2; dx++) {
                int xi = x0 + dx, yi = y0 + dy;
                bool v = (xi >= 0) & (xi < HW_) & (yi >= 0) & (yi < HW_);
                int xc = min(max(xi, 0), HW_ - 1);
                int yc = min(max(yi, 0), HW_ - 1);
                float cw = aw * (dy ? wy : 1.f - wy) * (dx ? wx : 1.f - wx);
                cw = v ? cw : 0.f;
                uint2 q = vp[(yc * HW_ + xc) * POS];
                float2 f0 = __bfloat1622float2(*(__nv_bfloat162*)&q.x);
                float2 f1 = __bfloat1622float2(*(__nv_bfloat162*)&q.y);
                a0 = fmaf(cw, f0.x, a0);
                a1 = fmaf(cw, f0.y, a1);
                a2 = fmaf(cw, f1.x, a2);
                a3 = fmaf(cw, f1.y, a3);
            }
        }
    }
    uint2 pk;
    asm("cvt.rn.bf16x2.f32 %0, %1, %2;" : "=r"(pk.x) : "f"(a1), "f"(a0));
    asm("cvt.rn.bf16x2.f32 %0, %1, %2;" : "=r"(pk.y) : "f"(a3), "f"(a2));
    ((uint2*)(g_attnb + (size_t)qi * DIM_ + h * HD_))[lane] = pk;
}

// ---------------- launch ----------------
extern "C" void kernel_launch(void* const* d_in, const int* in_sizes, int n_in,
                              void* d_out, int out_size)
{
    const float* query = (const float*)d_in[0];
    const float* refp  = (const float*)d_in[1];
    const float* feat  = (const float*)d_in[2];
    const float* lnw   = (const float*)d_in[5];
    const float* lnb   = (const float*)d_in[6];
    const float* vpw   = (const float*)d_in[7];
    const float* vpb   = (const float*)d_in[8];
    const float* offw  = (const float*)d_in[9];
    const float* offb  = (const float*)d_in[10];
    const float* aww   = (const float*)d_in[11];
    const float* awb   = (const float*)d_in[12];
    const float* outw  = (const float*)d_in[13];
    const float* outb  = (const float*)d_in[14];
    const float* gamma = (const float*)d_in[15];
    float* out = (float*)d_out;

    __nv_bfloat16 *p_featb, *p_valb, *p_attnb, *p_vpwt, *p_outwt;
    cudaGetSymbolAddress((void**)&p_featb, g_featb);
    cudaGetSymbolAddress((void**)&p_valb,  g_valb);
    cudaGetSymbolAddress((void**)&p_attnb, g_attnb);
    cudaGetSymbolAddress((void**)&p_vpwt,  g_vpwt);
    cudaGetSymbolAddress((void**)&p_outwt, g_outwt);

    const int SMEM = 3 * STAGE_B;   // 82944
    cudaFuncSetAttribute(gemm_bf16<0>, cudaFuncAttributeMaxDynamicSharedMemorySize, SMEM);
    cudaFuncSetAttribute(gemm_bf16<1>, cudaFuncAttributeMaxDynamicSharedMemorySize, SMEM);

    dim3 g0(NVT + 2, NROWS_ / 128);   // (14, 64): 12 value tiles + 2 logits tiles
    dim3 g1(NVT, NROWS_ / 128);       // (12, 64)

    prologue_kernel<<<PB_TOT, 384>>>(query, lnw, lnb, feat, vpw, outw,
                                     offw, offb, aww, awb);
    gemm_bf16<0><<<g0, 128, SMEM>>>(p_featb, p_vpwt, vpb, p_valb, DIM_, nullptr, nullptr);
    sample_kernel<<<NROWS_ * HEADS_ / 8, 256>>>(refp);
    gemm_bf16<1><<<g1, 128, SMEM>>>(p_attnb, p_outwt, outb, out, DIM_, query, gamma);
}